// round 1
// baseline (speedup 1.0000x reference)
#include <cuda_runtime.h>
#include <math.h>

// Problem dims (fixed by setup_inputs)
#define BB 2
#define NN 4096
#define MM 32      // neighbors
#define DD 128
#define EE 64
#define NODES (BB*NN)
#define QK_STRIDE 512   // 64*3 + 64*5

// Scratch (no cudaMalloc allowed)
__device__ float g_q[(size_t)NODES * QK_STRIDE];
__device__ float g_k[(size_t)NODES * QK_STRIDE];

// ---------------------------------------------------------------------------
// Kernel 1: per-node projections q1,k1 (ml=3) and q2,k2 (ml=5)
//   q[e,m] = sum_d x[d,m] * W[d,e]
// 8 nodes per block; projection weights staged once in smem.
// ---------------------------------------------------------------------------
__global__ void __launch_bounds__(256) proj_kernel(
    const float* __restrict__ x1, const float* __restrict__ x2,
    const float* __restrict__ tq, const float* __restrict__ tk1,
    const float* __restrict__ tk2)
{
    extern __shared__ float sm[];
    float* s_tq  = sm;              // 8192
    float* s_tk1 = s_tq + 8192;     // 8192
    float* s_tk2 = s_tk1 + 8192;    // 8192
    float* s_x1  = s_tk2 + 8192;    // 512  [d][4] padded
    float* s_x2  = s_x1 + 512;      // 1024 [d][8] padded

    const int tid = threadIdx.x;

    {
        const float4* g0 = (const float4*)tq;
        const float4* g1 = (const float4*)tk1;
        const float4* g2 = (const float4*)tk2;
        float4* d0 = (float4*)s_tq; float4* d1 = (float4*)s_tk1; float4* d2 = (float4*)s_tk2;
        for (int i = tid; i < 2048; i += 256) { d0[i] = g0[i]; d1[i] = g1[i]; d2[i] = g2[i]; }
    }

    const int type = tid >> 6;            // 0:q1 1:k1 2:q2 3:k2
    const int e    = tid & 63;
    const float* W = (type == 1) ? s_tk1 : (type == 3) ? s_tk2 : s_tq;

    for (int nl = 0; nl < 8; nl++) {
        const int node = blockIdx.x * 8 + nl;
        __syncthreads();  // also covers the weight staging on first iter
        const float* gx1 = x1 + (size_t)node * (DD * 3);
        const float* gx2 = x2 + (size_t)node * (DD * 5);
        for (int i = tid; i < DD * 3; i += 256) { int d = i / 3; s_x1[d * 4 + (i - d * 3)] = gx1[i]; }
        for (int i = tid; i < DD * 5; i += 256) { int d = i / 5; s_x2[d * 8 + (i - d * 5)] = gx2[i]; }
        __syncthreads();

        if (type < 2) {
            float a0 = 0.f, a1 = 0.f, a2 = 0.f;
            #pragma unroll 8
            for (int d = 0; d < DD; d++) {
                float w = W[d * 64 + e];
                float4 xv = *(const float4*)&s_x1[d * 4];
                a0 += w * xv.x; a1 += w * xv.y; a2 += w * xv.z;
            }
            float* dst = ((type == 0) ? g_q : g_k) + (size_t)node * QK_STRIDE + e * 3;
            dst[0] = a0; dst[1] = a1; dst[2] = a2;
        } else {
            float a0 = 0.f, a1 = 0.f, a2 = 0.f, a3 = 0.f, a4 = 0.f;
            #pragma unroll 8
            for (int d = 0; d < DD; d++) {
                float w = W[d * 64 + e];
                float4 xa = *(const float4*)&s_x2[d * 8];
                float4 xb = *(const float4*)&s_x2[d * 8 + 4];
                a0 += w * xa.x; a1 += w * xa.y; a2 += w * xa.z; a3 += w * xa.w; a4 += w * xb.x;
            }
            float* dst = ((type == 2) ? g_q : g_k) + (size_t)node * QK_STRIDE + 192 + e * 5;
            dst[0] = a0; dst[1] = a1; dst[2] = a2; dst[3] = a3; dst[4] = a4;
        }
    }
}

// ---------------------------------------------------------------------------
// Kernel 2: per-node fused  gather-ip -> LayerNorm -> (sigmoid(W@E) + T@R)
// One block per node, 256 threads. edge_w/res_w resident in smem.
// ---------------------------------------------------------------------------
__global__ void __launch_bounds__(256) main_kernel(
    const float* __restrict__ t_ij, const int* __restrict__ nidx,
    const float* __restrict__ lnw, const float* __restrict__ edge_w,
    const float* __restrict__ res_w, float* __restrict__ out)
{
    extern __shared__ float sm[];
    float* s_ew = sm;                 // 16384
    float* s_rw = s_ew + 16384;       // 16384
    float* s_w  = s_rw + 16384;       // 4096  [32][128]
    float* s_t  = s_w + 4096;         // 4096  [32][128]
    float* s_q  = s_t + 4096;         // 512
    float* s_ln = s_q + 512;          // 128
    int*   s_idx = (int*)(s_ln + 128);// 32

    const int tid = threadIdx.x;
    const int node = blockIdx.x;
    const int batch = node >> 12;     // node / 4096

    {
        const float4* ge = (const float4*)edge_w;
        const float4* gr = (const float4*)res_w;
        float4* de = (float4*)s_ew; float4* dr = (float4*)s_rw;
        for (int i = tid; i < 4096; i += 256) { de[i] = ge[i]; dr[i] = gr[i]; }
        const float4* gt = (const float4*)(t_ij + (size_t)node * 4096);
        float4* dt = (float4*)s_t;
        for (int i = tid; i < 1024; i += 256) dt[i] = gt[i];
        if (tid < 128) {
            ((float4*)s_q)[tid] = ((const float4*)(g_q + (size_t)node * QK_STRIDE))[tid];
            s_ln[tid] = lnw[tid];
        }
        if (tid < 32) s_idx[tid] = nidx[(size_t)node * 32 + tid];
    }
    __syncthreads();

    // --- inner products: w[j][c], c<64 from ml=3 block, c>=64 from ml=5 block
    for (int it = tid; it < 4096; it += 256) {
        const int j = it >> 7, c = it & 127;
        const int nbr = s_idx[j];
        const float* kb = g_k + ((size_t)(batch * NN + nbr)) * QK_STRIDE;
        float acc;
        if (c < 64) {
            const int base = c * 3;
            acc = s_q[base] * kb[base] + s_q[base + 1] * kb[base + 1] + s_q[base + 2] * kb[base + 2];
        } else {
            const int base = 192 + (c - 64) * 5;
            acc = 0.f;
            #pragma unroll
            for (int m5 = 0; m5 < 5; m5++) acc += s_q[base + m5] * kb[base + m5];
        }
        s_w[it] = acc;
    }
    __syncthreads();

    // --- LayerNorm over 128, weight-only. 8 warps x 4 rows.
    const int wid = tid >> 5, lane = tid & 31;
    #pragma unroll
    for (int r = 0; r < 4; r++) {
        const int j = wid * 4 + r;
        float v0 = s_w[j * 128 + lane];
        float v1 = s_w[j * 128 + lane + 32];
        float v2 = s_w[j * 128 + lane + 64];
        float v3 = s_w[j * 128 + lane + 96];
        float s  = v0 + v1 + v2 + v3;
        float ss = v0 * v0 + v1 * v1 + v2 * v2 + v3 * v3;
        #pragma unroll
        for (int o = 16; o > 0; o >>= 1) {
            s  += __shfl_xor_sync(0xffffffffu, s,  o);
            ss += __shfl_xor_sync(0xffffffffu, ss, o);
        }
        const float mu  = s * (1.f / 128.f);
        const float var = ss * (1.f / 128.f) - mu * mu;
        const float sc  = rsqrtf(fmaxf(var, 0.f) + 1e-5f);
        s_w[j * 128 + lane]      = (v0 - mu) * sc * s_ln[lane];
        s_w[j * 128 + lane + 32] = (v1 - mu) * sc * s_ln[lane + 32];
        s_w[j * 128 + lane + 64] = (v2 - mu) * sc * s_ln[lane + 64];
        s_w[j * 128 + lane + 96] = (v3 - mu) * sc * s_ln[lane + 96];
    }
    __syncthreads();

    // --- two 32x128x128 GEMMs, 4j x 4d register tile per thread
    const int j0 = wid * 4;
    const int d0 = lane * 4;
    float4 ae[4] = {make_float4(0,0,0,0), make_float4(0,0,0,0), make_float4(0,0,0,0), make_float4(0,0,0,0)};
    float4 ar[4] = {make_float4(0,0,0,0), make_float4(0,0,0,0), make_float4(0,0,0,0), make_float4(0,0,0,0)};

    #pragma unroll 2
    for (int k = 0; k < 128; k += 4) {
        float4 wv[4], tv[4];
        #pragma unroll
        for (int jj = 0; jj < 4; jj++) {
            wv[jj] = *(const float4*)&s_w[(j0 + jj) * 128 + k];
            tv[jj] = *(const float4*)&s_t[(j0 + jj) * 128 + k];
        }
        #pragma unroll
        for (int kk = 0; kk < 4; kk++) {
            const float4 ew = *(const float4*)&s_ew[(k + kk) * 128 + d0];
            const float4 rw = *(const float4*)&s_rw[(k + kk) * 128 + d0];
            #pragma unroll
            for (int jj = 0; jj < 4; jj++) {
                const float w_ = (kk == 0) ? wv[jj].x : (kk == 1) ? wv[jj].y : (kk == 2) ? wv[jj].z : wv[jj].w;
                const float t_ = (kk == 0) ? tv[jj].x : (kk == 1) ? tv[jj].y : (kk == 2) ? tv[jj].z : tv[jj].w;
                ae[jj].x += w_ * ew.x; ae[jj].y += w_ * ew.y; ae[jj].z += w_ * ew.z; ae[jj].w += w_ * ew.w;
                ar[jj].x += t_ * rw.x; ar[jj].y += t_ * rw.y; ar[jj].z += t_ * rw.z; ar[jj].w += t_ * rw.w;
            }
        }
    }

    float* gout = out + (size_t)node * 4096;
    #pragma unroll
    for (int jj = 0; jj < 4; jj++) {
        float4 o;
        o.x = 1.f / (1.f + __expf(-ae[jj].x)) + ar[jj].x;
        o.y = 1.f / (1.f + __expf(-ae[jj].y)) + ar[jj].y;
        o.z = 1.f / (1.f + __expf(-ae[jj].z)) + ar[jj].z;
        o.w = 1.f / (1.f + __expf(-ae[jj].w)) + ar[jj].w;
        *(float4*)&gout[(j0 + jj) * 128 + d0] = o;
    }
}

// ---------------------------------------------------------------------------
extern "C" void kernel_launch(void* const* d_in, const int* in_sizes, int n_in,
                              void* d_out, int out_size)
{
    const float* t_ij = (const float*)d_in[0];
    const float* x1   = (const float*)d_in[1];
    const float* x2   = (const float*)d_in[2];
    const int*   nidx = (const int*)  d_in[3];
    const float* tq   = (const float*)d_in[4];
    const float* tk1  = (const float*)d_in[5];
    const float* tk2  = (const float*)d_in[6];
    const float* lnw  = (const float*)d_in[7];
    const float* ew   = (const float*)d_in[8];
    const float* rw   = (const float*)d_in[9];
    float* out = (float*)d_out;

    const int smem1 = (3 * 8192 + 512 + 1024) * (int)sizeof(float);
    const int smem2 = (2 * 16384 + 2 * 4096 + 512 + 128) * (int)sizeof(float) + 32 * (int)sizeof(int);
    cudaFuncSetAttribute(proj_kernel, cudaFuncAttributeMaxDynamicSharedMemorySize, smem1);
    cudaFuncSetAttribute(main_kernel, cudaFuncAttributeMaxDynamicSharedMemorySize, smem2);

    proj_kernel<<<NODES / 8, 256, smem1>>>(x1, x2, tq, tk1, tk2);
    main_kernel<<<NODES, 256, smem2>>>(t_ij, nidx, lnw, ew, rw, out);
}

// round 3
// speedup vs baseline: 1.9355x; 1.9355x over previous
#include <cuda_runtime.h>
#include <cuda_bf16.h>
#include <cstdint>

#define NNODES 8192
#define QK_STRIDE 512

// ------------------------------------------------------------------ scratch
__device__ __align__(16) float g_q[(size_t)NNODES * QK_STRIDE];
__device__ __align__(16) float g_k[(size_t)NNODES * QK_STRIDE];
// 4 tile-blocked bf16 weight images, 32KB each: [edge_h][edge_l][res_h][res_l]
// B layout [n][k] transposed, blocked for ldmatrix: off(n,k) =
//   ((n>>3)*8 + (k>>4))*256 + ((k>>3)&1)*128 + (n&7)*16 + (k&7)*2
__device__ __align__(16) unsigned char g_wtiles[4 * 32768];

// ------------------------------------------------------------------ helpers
__device__ __forceinline__ uint32_t smem_u32(const void* p) {
    uint32_t a;
    asm("{ .reg .u64 t; cvta.to.shared.u64 t, %1; cvt.u32.u64 %0, t; }" : "=r"(a) : "l"(p));
    return a;
}
__device__ __forceinline__ uint32_t pack_bf16x2(float a, float b) {  // lo=bf16(a), hi=bf16(b)
    uint32_t p;
    asm("cvt.rn.bf16x2.f32 %0, %1, %2;" : "=r"(p) : "f"(b), "f"(a));
    return p;
}
#define LDSM_X4(r0, r1, r2, r3, addr) \
    asm volatile("ldmatrix.sync.aligned.m8n8.x4.shared.b16 {%0,%1,%2,%3}, [%4];" \
        : "=r"(r0), "=r"(r1), "=r"(r2), "=r"(r3) : "r"(addr))
#define LDSM_X2(r0, r1, addr) \
    asm volatile("ldmatrix.sync.aligned.m8n8.x2.shared.b16 {%0,%1}, [%2];" \
        : "=r"(r0), "=r"(r1) : "r"(addr))
#define MMA_BF16(c, a0, a1, a2, a3, b0, b1) \
    asm volatile("mma.sync.aligned.m16n8k16.row.col.f32.bf16.bf16.f32 " \
        "{%0,%1,%2,%3}, {%4,%5,%6,%7}, {%8,%9}, {%0,%1,%2,%3};" \
        : "+f"((c)[0]), "+f"((c)[1]), "+f"((c)[2]), "+f"((c)[3]) \
        : "r"(a0), "r"(a1), "r"(a2), "r"(a3), "r"(b0), "r"(b1))
#define CP_ASYNC16(saddr, gptr) \
    asm volatile("cp.async.cg.shared.global [%0], [%1], 16;" :: "r"(saddr), "l"(gptr))
#define CP_COMMIT() asm volatile("cp.async.commit_group;")
#define CP_WAIT0()  asm volatile("cp.async.wait_group 0;" ::: "memory")

// ------------------------------------------------------------------ smem map (bytes)
#define SW_WT  0          // 131072: Eh,El,Rh,Rl (32KB each)
#define SW_WH  131072     // 16384
#define SW_WL  147456     // 16384
#define SW_TH  163840     // 16384
#define SW_TL  180224     // 16384
#define SW_KS  196608     // 32768: 16 gathered k-rows x 512 f32
#define SW_Q   229376     // 2048
#define SW_IDX 231424     // 256 (idx for both nodes)
#define SMEM_B 231680

// A-tile blocked offset (bytes): m in [0,64), k in [0,128)
__device__ __forceinline__ uint32_t a_off(int m, int k) {
    return (uint32_t)(((m >> 3) * 16 + (k >> 3)) * 128 + ((m & 7) << 4) + ((k & 7) << 1));
}

// ------------------------------------------------------------------ kernel 0: weight split
__global__ void __launch_bounds__(256) wsplit_kernel(const float* __restrict__ ew,
                                                     const float* __restrict__ rw) {
    int id = blockIdx.x * 256 + threadIdx.x;      // 0..32767
    int w = id >> 14, k = (id >> 7) & 127, n = id & 127;
    float v = (w ? rw : ew)[k * 128 + n];         // B[n][k] = W[k][n]
    uint32_t ph = pack_bf16x2(v, 0.f);
    float hf = __uint_as_float(ph << 16);
    uint32_t pl = pack_bf16x2(v - hf, 0.f);
    uint32_t off = (uint32_t)(((n >> 3) * 8 + (k >> 4)) * 256 + (((k >> 3) & 1) << 7)
                              + ((n & 7) << 4) + ((k & 7) << 1));
    *(uint16_t*)(g_wtiles + (size_t)(w * 2 + 0) * 32768 + off) = (uint16_t)(ph & 0xffffu);
    *(uint16_t*)(g_wtiles + (size_t)(w * 2 + 1) * 32768 + off) = (uint16_t)(pl & 0xffffu);
}

// ------------------------------------------------------------------ kernel 1: projections
__global__ void __launch_bounds__(128) proj_kernel(
    const float* __restrict__ x1, const float* __restrict__ x2,
    const float* __restrict__ tq, const float* __restrict__ tk1,
    const float* __restrict__ tk2)
{
    __shared__ float sx[1024];
    const int node = blockIdx.x, tid = threadIdx.x;
    const float* px1 = x1 + (size_t)node * 384;
    const float* px2 = x2 + (size_t)node * 640;
    for (int i = tid; i < 1024; i += 128)
        sx[i] = (i < 384) ? __ldg(px1 + i) : __ldg(px2 + (i - 384));
    __syncthreads();

    const int deg = tid >> 6, e = tid & 63;
    if (deg == 0) {
        float q0=0,q1=0,q2=0,k0=0,k1=0,k2=0;
        #pragma unroll 4
        for (int d = 0; d < 128; ++d) {
            float wq = __ldg(tq + d * 64 + e), wk = __ldg(tk1 + d * 64 + e);
            float a = sx[d*3], b = sx[d*3+1], c = sx[d*3+2];
            q0 += wq*a; q1 += wq*b; q2 += wq*c;
            k0 += wk*a; k1 += wk*b; k2 += wk*c;
        }
        float* oq = g_q + (size_t)node * QK_STRIDE + e * 3;
        float* ok = g_k + (size_t)node * QK_STRIDE + e * 3;
        oq[0]=q0; oq[1]=q1; oq[2]=q2; ok[0]=k0; ok[1]=k1; ok[2]=k2;
    } else {
        float q[5] = {0,0,0,0,0}, kv[5] = {0,0,0,0,0};
        #pragma unroll 2
        for (int d = 0; d < 128; ++d) {
            float wq = __ldg(tq + d * 64 + e), wk = __ldg(tk2 + d * 64 + e);
            #pragma unroll
            for (int m = 0; m < 5; ++m) {
                float xv = sx[384 + d*5 + m];
                q[m] += wq * xv; kv[m] += wk * xv;
            }
        }
        float* oq = g_q + (size_t)node * QK_STRIDE + 192 + e * 5;
        float* ok = g_k + (size_t)node * QK_STRIDE + 192 + e * 5;
        #pragma unroll
        for (int m = 0; m < 5; ++m) { oq[m] = q[m]; ok[m] = kv[m]; }
    }
}

// ------------------------------------------------------------------ kernel 2: fused main
__global__ void __launch_bounds__(256, 1) main_kernel(
    const float* __restrict__ t_ij, const int* __restrict__ nidx,
    const float* __restrict__ lnw, float* __restrict__ out)
{
    extern __shared__ char smem[];
    const uint32_t sb = smem_u32(smem);
    const int tid = threadIdx.x, lane = tid & 31, wid = tid >> 5;
    const int blk = blockIdx.x;
    const int batch = (blk * 2) >> 12;
    float* kst = (float*)(smem + SW_KS);
    float* s_q = (float*)(smem + SW_Q);
    int*   s_ix = (int*)(smem + SW_IDX);

    // ---- 1. weights -> smem via cp.async (overlapped with everything below)
    {
        const char* gsrc = (const char*)g_wtiles;
        #pragma unroll
        for (int i = 0; i < 32; ++i) {
            uint32_t off = (uint32_t)(i * 4096 + tid * 16);
            CP_ASYNC16(sb + SW_WT + off, gsrc + off);
        }
        CP_COMMIT();
    }

    // ---- 2. neighbor indices for both nodes
    if (tid < 64) s_ix[tid] = __ldg(nidx + blk * 64 + tid);

    // ---- 3. T -> bf16 hi/lo directly from global
    {
        const float* tb = t_ij + (size_t)blk * 8192;
        #pragma unroll
        for (int it = 0; it < 16; ++it) {
            int i = it * 256 + tid;              // 4096 pairs
            int m = i >> 6, c0 = (i & 63) * 2;
            float2 v = __ldg((const float2*)(tb + m * 128 + c0));
            uint32_t ph = pack_bf16x2(v.x, v.y);
            float h0 = __uint_as_float(ph << 16);
            float h1 = __uint_as_float(ph & 0xffff0000u);
            uint32_t pl = pack_bf16x2(v.x - h0, v.y - h1);
            uint32_t off = a_off(m, c0);
            *(uint32_t*)(smem + SW_TH + off) = ph;
            *(uint32_t*)(smem + SW_TL + off) = pl;
        }
    }

    // ---- 4. per node: gather k, inner products, LayerNorm, bf16 split -> Wh/Wl
    const float gl0 = __ldg(lnw + 2 * lane), gl1 = __ldg(lnw + 2 * lane + 1);
    const float gl2 = __ldg(lnw + 64 + 2 * lane), gl3 = __ldg(lnw + 65 + 2 * lane);
    for (int nl = 0; nl < 2; ++nl) {
        const int node = blk * 2 + nl;
        for (int ch = 0; ch < 2; ++ch) {
            __syncthreads();   // idx visible (first iter); kstage free; prev q usage done
            // gather 16 rows of k (512 f32 each)
            const int* sidx = s_ix + nl * 32 + ch * 16;
            #pragma unroll
            for (int it = 0; it < 8; ++it) {
                int i4 = it * 256 + tid;
                int jj = i4 >> 7, c4 = i4 & 127;
                int nbr = sidx[jj];
                ((float4*)kst)[jj * 128 + c4] =
                    __ldg((const float4*)g_k + (size_t)(batch * 4096 + nbr) * 128 + c4);
            }
            if (ch == 0 && tid < 128)
                ((float4*)s_q)[tid] = __ldg((const float4*)(g_q + (size_t)node * 512) + tid);
            __syncthreads();
            // ip + LN + convert: warp handles rows 2*wid, 2*wid+1 of this chunk
            #pragma unroll
            for (int rr = 0; rr < 2; ++rr) {
                const int r = wid * 2 + rr;
                const float* kr = kst + r * 512;
                const int c0 = 2 * lane;
                int b = 3 * c0;
                float v0 = s_q[b]*kr[b] + s_q[b+1]*kr[b+1] + s_q[b+2]*kr[b+2];
                float v1 = s_q[b+3]*kr[b+3] + s_q[b+4]*kr[b+4] + s_q[b+5]*kr[b+5];
                int b2 = 192 + 10 * lane;
                float v2 = 0.f, v3 = 0.f;
                #pragma unroll
                for (int m5 = 0; m5 < 5; ++m5) {
                    v2 += s_q[b2+m5] * kr[b2+m5];
                    v3 += s_q[b2+5+m5] * kr[b2+5+m5];
                }
                float s  = v0+v1+v2+v3;
                float ss = v0*v0+v1*v1+v2*v2+v3*v3;
                #pragma unroll
                for (int o = 16; o > 0; o >>= 1) {
                    s  += __shfl_xor_sync(0xffffffffu, s,  o);
                    ss += __shfl_xor_sync(0xffffffffu, ss, o);
                }
                const float mu = s * (1.f/128.f);
                const float var = ss * (1.f/128.f) - mu*mu;
                const float sc = rsqrtf(fmaxf(var, 0.f) + 1e-5f);
                v0 = (v0-mu)*sc*gl0; v1 = (v1-mu)*sc*gl1;
                v2 = (v2-mu)*sc*gl2; v3 = (v3-mu)*sc*gl3;
                const int m = nl * 32 + ch * 16 + r;
                uint32_t ph = pack_bf16x2(v0, v1);
                float h0 = __uint_as_float(ph << 16), h1 = __uint_as_float(ph & 0xffff0000u);
                uint32_t pl = pack_bf16x2(v0 - h0, v1 - h1);
                uint32_t off = a_off(m, c0);
                *(uint32_t*)(smem + SW_WH + off) = ph;
                *(uint32_t*)(smem + SW_WL + off) = pl;
                ph = pack_bf16x2(v2, v3);
                h0 = __uint_as_float(ph << 16); h1 = __uint_as_float(ph & 0xffff0000u);
                pl = pack_bf16x2(v2 - h0, v3 - h1);
                off = a_off(m, 64 + c0);
                *(uint32_t*)(smem + SW_WH + off) = ph;
                *(uint32_t*)(smem + SW_WL + off) = pl;
            }
        }
    }
    CP_WAIT0();
    __syncthreads();

    // ---- 5. GEMMs via mma.sync bf16 (hi/lo 3-pass)
    const int mbase = (wid & 3) * 16;
    const int nhalf = wid >> 2;
    // per-thread ldmatrix address pieces
    const uint32_t a_thr = (uint32_t)(((mbase * 2 + 16 * ((lane >> 3) & 1) + (lane >> 4)) << 7)
                                      + ((lane & 7) << 4));
    const uint32_t b_thr = (uint32_t)(((((lane & 15) >> 3)) << 7) + ((lane & 7) << 4));

    uint32_t Ah[32], Al[32];
    #pragma unroll
    for (int ks = 0; ks < 8; ++ks) {
        uint32_t ad = sb + SW_WH + a_thr + (uint32_t)(ks * 256);
        LDSM_X4(Ah[ks*4], Ah[ks*4+1], Ah[ks*4+2], Ah[ks*4+3], ad);
        ad = sb + SW_WL + a_thr + (uint32_t)(ks * 256);
        LDSM_X4(Al[ks*4], Al[ks*4+1], Al[ks*4+2], Al[ks*4+3], ad);
    }
    float accE[32];
    #pragma unroll
    for (int i = 0; i < 32; ++i) accE[i] = 0.f;
    // edge: accE += Wh*Eh + Wl*Eh + Wh*El
    #pragma unroll
    for (int ks = 0; ks < 8; ++ks) {
        #pragma unroll
        for (int nt = 0; nt < 8; ++nt) {
            const int tn = nhalf * 8 + nt;
            uint32_t b0, b1;
            LDSM_X2(b0, b1, sb + SW_WT + (uint32_t)((tn * 8 + ks) << 8) + b_thr);
            MMA_BF16(&accE[nt*4], Ah[ks*4], Ah[ks*4+1], Ah[ks*4+2], Ah[ks*4+3], b0, b1);
            MMA_BF16(&accE[nt*4], Al[ks*4], Al[ks*4+1], Al[ks*4+2], Al[ks*4+3], b0, b1);
        }
    }
    #pragma unroll
    for (int ks = 0; ks < 8; ++ks) {
        #pragma unroll
        for (int nt = 0; nt < 8; ++nt) {
            const int tn = nhalf * 8 + nt;
            uint32_t b0, b1;
            LDSM_X2(b0, b1, sb + SW_WT + 32768u + (uint32_t)((tn * 8 + ks) << 8) + b_thr);
            MMA_BF16(&accE[nt*4], Ah[ks*4], Ah[ks*4+1], Ah[ks*4+2], Ah[ks*4+3], b0, b1);
        }
    }
    // reload A frags with T
    #pragma unroll
    for (int ks = 0; ks < 8; ++ks) {
        uint32_t ad = sb + SW_TH + a_thr + (uint32_t)(ks * 256);
        LDSM_X4(Ah[ks*4], Ah[ks*4+1], Ah[ks*4+2], Ah[ks*4+3], ad);
        ad = sb + SW_TL + a_thr + (uint32_t)(ks * 256);
        LDSM_X4(Al[ks*4], Al[ks*4+1], Al[ks*4+2], Al[ks*4+3], ad);
    }
    float accR[32];
    #pragma unroll
    for (int i = 0; i < 32; ++i) accR[i] = 0.f;
    #pragma unroll
    for (int ks = 0; ks < 8; ++ks) {
        #pragma unroll
        for (int nt = 0; nt < 8; ++nt) {
            const int tn = nhalf * 8 + nt;
            uint32_t b0, b1;
            LDSM_X2(b0, b1, sb + SW_WT + 65536u + (uint32_t)((tn * 8 + ks) << 8) + b_thr);
            MMA_BF16(&accR[nt*4], Ah[ks*4], Ah[ks*4+1], Ah[ks*4+2], Ah[ks*4+3], b0, b1);
            MMA_BF16(&accR[nt*4], Al[ks*4], Al[ks*4+1], Al[ks*4+2], Al[ks*4+3], b0, b1);
        }
    }
    #pragma unroll
    for (int ks = 0; ks < 8; ++ks) {
        #pragma unroll
        for (int nt = 0; nt < 8; ++nt) {
            const int tn = nhalf * 8 + nt;
            uint32_t b0, b1;
            LDSM_X2(b0, b1, sb + SW_WT + 98304u + (uint32_t)((tn * 8 + ks) << 8) + b_thr);
            MMA_BF16(&accR[nt*4], Ah[ks*4], Ah[ks*4+1], Ah[ks*4+2], Ah[ks*4+3], b0, b1);
        }
    }

    // ---- 6. epilogue: sigmoid(edge) + res -> global
    {
        float* ob = out + (size_t)blk * 8192;
        const int row0 = mbase + (lane >> 2);
        #pragma unroll
        for (int nt = 0; nt < 8; ++nt) {
            const int col = nhalf * 64 + nt * 8 + (lane & 3) * 2;
            float o0 = 1.f / (1.f + __expf(-accE[nt*4+0])) + accR[nt*4+0];
            float o1 = 1.f / (1.f + __expf(-accE[nt*4+1])) + accR[nt*4+1];
            float o2 = 1.f / (1.f + __expf(-accE[nt*4+2])) + accR[nt*4+2];
            float o3 = 1.f / (1.f + __expf(-accE[nt*4+3])) + accR[nt*4+3];
            *(float2*)(ob + row0 * 128 + col)       = make_float2(o0, o1);
            *(float2*)(ob + (row0 + 8) * 128 + col) = make_float2(o2, o3);
        }
    }
}

// ------------------------------------------------------------------ launch
extern "C" void kernel_launch(void* const* d_in, const int* in_sizes, int n_in,
                              void* d_out, int out_size)
{
    const float* t_ij = (const float*)d_in[0];
    const float* x1   = (const float*)d_in[1];
    const float* x2   = (const float*)d_in[2];
    const int*   nidx = (const int*)  d_in[3];
    const float* tq   = (const float*)d_in[4];
    const float* tk1  = (const float*)d_in[5];
    const float* tk2  = (const float*)d_in[6];
    const float* lnw  = (const float*)d_in[7];
    const float* ew   = (const float*)d_in[8];
    const float* rw   = (const float*)d_in[9];
    float* out = (float*)d_out;

    cudaFuncSetAttribute(main_kernel, cudaFuncAttributeMaxDynamicSharedMemorySize, SMEM_B);

    wsplit_kernel<<<128, 256>>>(ew, rw);
    proj_kernel<<<NNODES, 128>>>(x1, x2, tq, tk1, tk2);
    main_kernel<<<NNODES / 2, 256, SMEM_B>>>(t_ij, nidx, lnw, out);
}

// round 4
// speedup vs baseline: 2.6100x; 1.3485x over previous
#include <cuda_runtime.h>
#include <cuda_bf16.h>
#include <cstdint>

#define NNODES 8192
#define QK_STRIDE 512
#define NTILES 4096          // node pairs

// ------------------------------------------------------------------ scratch
__device__ __align__(16) float g_q[(size_t)NNODES * QK_STRIDE];
__device__ __align__(16) float g_k[(size_t)NNODES * QK_STRIDE];
// 4 tile-blocked bf16 weight images, 32KB each: [edge_h][edge_l][res_h][res_l]
__device__ __align__(16) unsigned char g_wtiles[4 * 32768];

// ------------------------------------------------------------------ helpers
__device__ __forceinline__ uint32_t smem_u32(const void* p) {
    uint32_t a;
    asm("{ .reg .u64 t; cvta.to.shared.u64 t, %1; cvt.u32.u64 %0, t; }" : "=r"(a) : "l"(p));
    return a;
}
__device__ __forceinline__ uint32_t pack_bf16x2(float a, float b) {  // lo=bf16(a), hi=bf16(b)
    uint32_t p;
    asm("cvt.rn.bf16x2.f32 %0, %1, %2;" : "=r"(p) : "f"(b), "f"(a));
    return p;
}
#define LDSM_X4(r0, r1, r2, r3, addr) \
    asm volatile("ldmatrix.sync.aligned.m8n8.x4.shared.b16 {%0,%1,%2,%3}, [%4];" \
        : "=r"(r0), "=r"(r1), "=r"(r2), "=r"(r3) : "r"(addr))
#define LDSM_X2(r0, r1, addr) \
    asm volatile("ldmatrix.sync.aligned.m8n8.x2.shared.b16 {%0,%1}, [%2];" \
        : "=r"(r0), "=r"(r1) : "r"(addr))
#define MMA_BF16(c, a0, a1, a2, a3, b0, b1) \
    asm volatile("mma.sync.aligned.m16n8k16.row.col.f32.bf16.bf16.f32 " \
        "{%0,%1,%2,%3}, {%4,%5,%6,%7}, {%8,%9}, {%0,%1,%2,%3};" \
        : "+f"((c)[0]), "+f"((c)[1]), "+f"((c)[2]), "+f"((c)[3]) \
        : "r"(a0), "r"(a1), "r"(a2), "r"(a3), "r"(b0), "r"(b1))
#define CP_ASYNC16(saddr, gptr) \
    asm volatile("cp.async.cg.shared.global [%0], [%1], 16;" :: "r"(saddr), "l"(gptr))
#define CP_COMMIT() asm volatile("cp.async.commit_group;")
#define CP_WAIT0()  asm volatile("cp.async.wait_group 0;" ::: "memory")
#define CP_WAIT1()  asm volatile("cp.async.wait_group 1;" ::: "memory")

// ------------------------------------------------------------------ smem map (bytes)
#define SW_WT  0          // 131072: Eh,El,Rh,Rl (32KB each)
#define SW_WH  131072     // 16384
#define SW_WL  147456     // 16384
#define SW_KB0 163840     // 33024: 16 rows x 516 f32
#define SW_KB1 196864     // 33024
#define SW_Q   229888     // 2048 (one node's q)
#define SW_IDX 231936     // 256
#define SMEM_B 232192

// A-tile blocked offset (bytes): m in [0,64), k in [0,128)
__device__ __forceinline__ uint32_t a_off(int m, int k) {
    return (uint32_t)(((m >> 3) * 16 + (k >> 3)) * 128 + ((m & 7) << 4) + ((k & 7) << 1));
}

// ------------------------------------------------------------------ kernel 0: weight split
__global__ void __launch_bounds__(256) wsplit_kernel(const float* __restrict__ ew,
                                                     const float* __restrict__ rw) {
    int id = blockIdx.x * 256 + threadIdx.x;      // 0..32767
    int w = id >> 14, k = (id >> 7) & 127, n = id & 127;
    float v = (w ? rw : ew)[k * 128 + n];         // B[n][k] = W[k][n]
    uint32_t ph = pack_bf16x2(v, 0.f);
    float hf = __uint_as_float(ph << 16);
    uint32_t pl = pack_bf16x2(v - hf, 0.f);
    uint32_t off = (uint32_t)(((n >> 3) * 8 + (k >> 4)) * 256 + (((k >> 3) & 1) << 7)
                              + ((n & 7) << 4) + ((k & 7) << 1));
    *(uint16_t*)(g_wtiles + (size_t)(w * 2 + 0) * 32768 + off) = (uint16_t)(ph & 0xffffu);
    *(uint16_t*)(g_wtiles + (size_t)(w * 2 + 1) * 32768 + off) = (uint16_t)(pl & 0xffffu);
}

// ------------------------------------------------------------------ kernel 1: projections
__global__ void __launch_bounds__(128) proj_kernel(
    const float* __restrict__ x1, const float* __restrict__ x2,
    const float* __restrict__ tq, const float* __restrict__ tk1,
    const float* __restrict__ tk2)
{
    __shared__ float sx[1024];
    const int node = blockIdx.x, tid = threadIdx.x;
    const float* px1 = x1 + (size_t)node * 384;
    const float* px2 = x2 + (size_t)node * 640;
    for (int i = tid; i < 1024; i += 128)
        sx[i] = (i < 384) ? __ldg(px1 + i) : __ldg(px2 + (i - 384));
    __syncthreads();

    const int deg = tid >> 6, e = tid & 63;
    if (deg == 0) {
        float q0=0,q1=0,q2=0,k0=0,k1=0,k2=0;
        #pragma unroll 4
        for (int d = 0; d < 128; ++d) {
            float wq = __ldg(tq + d * 64 + e), wk = __ldg(tk1 + d * 64 + e);
            float a = sx[d*3], b = sx[d*3+1], c = sx[d*3+2];
            q0 += wq*a; q1 += wq*b; q2 += wq*c;
            k0 += wk*a; k1 += wk*b; k2 += wk*c;
        }
        float* oq = g_q + (size_t)node * QK_STRIDE + e * 3;
        float* ok = g_k + (size_t)node * QK_STRIDE + e * 3;
        oq[0]=q0; oq[1]=q1; oq[2]=q2; ok[0]=k0; ok[1]=k1; ok[2]=k2;
    } else {
        float q[5] = {0,0,0,0,0}, kv[5] = {0,0,0,0,0};
        #pragma unroll 2
        for (int d = 0; d < 128; ++d) {
            float wq = __ldg(tq + d * 64 + e), wk = __ldg(tk2 + d * 64 + e);
            #pragma unroll
            for (int m = 0; m < 5; ++m) {
                float xv = sx[384 + d*5 + m];
                q[m] += wq * xv; kv[m] += wk * xv;
            }
        }
        float* oq = g_q + (size_t)node * QK_STRIDE + 192 + e * 5;
        float* ok = g_k + (size_t)node * QK_STRIDE + 192 + e * 5;
        #pragma unroll
        for (int m = 0; m < 5; ++m) { oq[m] = q[m]; ok[m] = kv[m]; }
    }
}

// ------------------------------------------------------------------ kernel 2: persistent fused main
__global__ void __launch_bounds__(256, 1) main_kernel(
    const float* __restrict__ t_ij, const int* __restrict__ nidx,
    const float* __restrict__ lnw, float* __restrict__ out)
{
    extern __shared__ char smem[];
    const uint32_t sb = smem_u32(smem);
    const int tid = threadIdx.x, lane = tid & 31, wid = tid >> 5;
    float* s_q = (float*)(smem + SW_Q);
    int*   s_ix = (int*)(smem + SW_IDX);

    // ---- stage split weights ONCE (128 KB)
    {
        const char* gsrc = (const char*)g_wtiles;
        #pragma unroll
        for (int i = 0; i < 32; ++i) {
            uint32_t off = (uint32_t)(i * 4096 + tid * 16);
            CP_ASYNC16(sb + SW_WT + off, gsrc + off);
        }
        CP_COMMIT();
    }
    const float gl0 = __ldg(lnw + 2 * lane), gl1 = __ldg(lnw + 2 * lane + 1);
    const float gl2 = __ldg(lnw + 64 + 2 * lane), gl3 = __ldg(lnw + 65 + 2 * lane);
    CP_WAIT0();
    __syncthreads();

    const int mbase = (wid & 3) * 16;
    const int nhalf = wid >> 2;
    const uint32_t a_thr = (uint32_t)(((mbase * 2 + 16 * ((lane >> 3) & 1) + (lane >> 4)) << 7)
                                      + ((lane & 7) << 4));
    const uint32_t b_thr = (uint32_t)(((((lane & 15) >> 3)) << 7) + ((lane & 7) << 4));
    const int r0  = mbase + (lane >> 2);       // T-frag row
    const int cb  = (lane & 3) * 2;            // T-frag col base

    for (int tile = blockIdx.x; tile < NTILES; tile += gridDim.x) {
        const int batch = tile >> 11;
        __syncthreads();                              // prev tile fully done
        if (tid < 64) s_ix[tid] = __ldg(nidx + tile * 64 + tid);
        __syncthreads();

        // ---- pipelined gather (cp.async, 2 buffers) + ip + LN
        {
            // prologue: chunk 0
            #pragma unroll
            for (int it = 0; it < 8; ++it) {
                int s = it * 256 + tid;
                int jj = s >> 7, part = s & 127;
                const char* src = (const char*)g_k
                    + ((size_t)(batch * 4096 + s_ix[jj]) * 2048 + (size_t)part * 16);
                CP_ASYNC16(sb + SW_KB0 + (uint32_t)(jj * 2064 + part * 16), src);
            }
            CP_COMMIT();
        }
        #pragma unroll
        for (int ch = 0; ch < 4; ++ch) {
            if (ch < 3) {
                const int nc = ch + 1;
                const uint32_t kb = (nc & 1) ? SW_KB1 : SW_KB0;
                #pragma unroll
                for (int it = 0; it < 8; ++it) {
                    int s = it * 256 + tid;
                    int jj = s >> 7, part = s & 127;
                    const char* src = (const char*)g_k
                        + ((size_t)(batch * 4096 + s_ix[nc * 16 + jj]) * 2048 + (size_t)part * 16);
                    CP_ASYNC16(sb + kb + (uint32_t)(jj * 2064 + part * 16), src);
                }
                CP_COMMIT();
            }
            if (!(ch & 1) && tid < 128)
                ((float4*)s_q)[tid] =
                    __ldg((const float4*)(g_q + (size_t)(tile * 2 + (ch >> 1)) * 512) + tid);
            if (ch < 3) CP_WAIT1(); else CP_WAIT0();
            __syncthreads();

            const float* kbuf = (const float*)(smem + ((ch & 1) ? SW_KB1 : SW_KB0));
            #pragma unroll
            for (int rr = 0; rr < 2; ++rr) {
                const int r = wid * 2 + rr;
                const float* kr = kbuf + r * 516;
                const int c0 = 2 * lane;
                int b = 3 * c0;
                float v0 = s_q[b]*kr[b] + s_q[b+1]*kr[b+1] + s_q[b+2]*kr[b+2];
                float v1 = s_q[b+3]*kr[b+3] + s_q[b+4]*kr[b+4] + s_q[b+5]*kr[b+5];
                int b2 = 192 + 10 * lane;
                float v2 = 0.f, v3 = 0.f;
                #pragma unroll
                for (int m5 = 0; m5 < 5; ++m5) {
                    v2 += s_q[b2+m5] * kr[b2+m5];
                    v3 += s_q[b2+5+m5] * kr[b2+5+m5];
                }
                float s  = v0+v1+v2+v3;
                float ss = v0*v0+v1*v1+v2*v2+v3*v3;
                #pragma unroll
                for (int o = 16; o > 0; o >>= 1) {
                    s  += __shfl_xor_sync(0xffffffffu, s,  o);
                    ss += __shfl_xor_sync(0xffffffffu, ss, o);
                }
                const float mu = s * (1.f/128.f);
                const float var = ss * (1.f/128.f) - mu*mu;
                const float sc = rsqrtf(fmaxf(var, 0.f) + 1e-5f);
                v0 = (v0-mu)*sc*gl0; v1 = (v1-mu)*sc*gl1;
                v2 = (v2-mu)*sc*gl2; v3 = (v3-mu)*sc*gl3;
                const int m = ch * 16 + r;
                uint32_t ph = pack_bf16x2(v0, v1);
                float h0 = __uint_as_float(ph << 16), h1 = __uint_as_float(ph & 0xffff0000u);
                uint32_t pl = pack_bf16x2(v0 - h0, v1 - h1);
                uint32_t off = a_off(m, c0);
                *(uint32_t*)(smem + SW_WH + off) = ph;
                *(uint32_t*)(smem + SW_WL + off) = pl;
                ph = pack_bf16x2(v2, v3);
                h0 = __uint_as_float(ph << 16); h1 = __uint_as_float(ph & 0xffff0000u);
                pl = pack_bf16x2(v2 - h0, v3 - h1);
                off = a_off(m, 64 + c0);
                *(uint32_t*)(smem + SW_WH + off) = ph;
                *(uint32_t*)(smem + SW_WL + off) = pl;
            }
            __syncthreads();
        }

        // ---- edge GEMM (A = normalized W from smem frags)
        uint32_t Ah[32], Al[32];
        #pragma unroll
        for (int ks = 0; ks < 8; ++ks) {
            uint32_t ad = sb + SW_WH + a_thr + (uint32_t)(ks * 256);
            LDSM_X4(Ah[ks*4], Ah[ks*4+1], Ah[ks*4+2], Ah[ks*4+3], ad);
            ad = sb + SW_WL + a_thr + (uint32_t)(ks * 256);
            LDSM_X4(Al[ks*4], Al[ks*4+1], Al[ks*4+2], Al[ks*4+3], ad);
        }
        float accE[32], accR[32];
        #pragma unroll
        for (int i = 0; i < 32; ++i) { accE[i] = 0.f; accR[i] = 0.f; }
        #pragma unroll
        for (int ks = 0; ks < 8; ++ks) {
            #pragma unroll
            for (int nt = 0; nt < 8; ++nt) {
                const uint32_t tb_off = (uint32_t)(((nhalf * 8 + nt) * 8 + ks) << 8) + b_thr;
                uint32_t b0, b1, c0, c1;
                LDSM_X2(b0, b1, sb + SW_WT + tb_off);            // Eh
                MMA_BF16(&accE[nt*4], Ah[ks*4], Ah[ks*4+1], Ah[ks*4+2], Ah[ks*4+3], b0, b1);
                MMA_BF16(&accE[nt*4], Al[ks*4], Al[ks*4+1], Al[ks*4+2], Al[ks*4+3], b0, b1);
                LDSM_X2(c0, c1, sb + SW_WT + 32768u + tb_off);   // El
                MMA_BF16(&accE[nt*4], Ah[ks*4], Ah[ks*4+1], Ah[ks*4+2], Ah[ks*4+3], c0, c1);
            }
        }

        // ---- res GEMM (A = T loaded straight from global into frags)
        const float* tb = t_ij + (size_t)tile * 8192;
        #pragma unroll
        for (int ks = 0; ks < 8; ++ks) {
            const int col = ks * 16 + cb;
            float2 v0 = __ldg((const float2*)(tb + r0 * 128 + col));
            float2 v1 = __ldg((const float2*)(tb + (r0 + 8) * 128 + col));
            float2 v2 = __ldg((const float2*)(tb + r0 * 128 + col + 8));
            float2 v3 = __ldg((const float2*)(tb + (r0 + 8) * 128 + col + 8));
            uint32_t th0 = pack_bf16x2(v0.x, v0.y);
            uint32_t th1 = pack_bf16x2(v1.x, v1.y);
            uint32_t th2 = pack_bf16x2(v2.x, v2.y);
            uint32_t th3 = pack_bf16x2(v3.x, v3.y);
            uint32_t tl0 = pack_bf16x2(v0.x - __uint_as_float(th0 << 16), v0.y - __uint_as_float(th0 & 0xffff0000u));
            uint32_t tl1 = pack_bf16x2(v1.x - __uint_as_float(th1 << 16), v1.y - __uint_as_float(th1 & 0xffff0000u));
            uint32_t tl2 = pack_bf16x2(v2.x - __uint_as_float(th2 << 16), v2.y - __uint_as_float(th2 & 0xffff0000u));
            uint32_t tl3 = pack_bf16x2(v3.x - __uint_as_float(th3 << 16), v3.y - __uint_as_float(th3 & 0xffff0000u));
            #pragma unroll
            for (int nt = 0; nt < 8; ++nt) {
                const uint32_t tb_off = (uint32_t)(((nhalf * 8 + nt) * 8 + ks) << 8) + b_thr;
                uint32_t b0, b1, c0, c1;
                LDSM_X2(b0, b1, sb + SW_WT + 65536u + tb_off);   // Rh
                MMA_BF16(&accR[nt*4], th0, th1, th2, th3, b0, b1);
                MMA_BF16(&accR[nt*4], tl0, tl1, tl2, tl3, b0, b1);
                LDSM_X2(c0, c1, sb + SW_WT + 98304u + tb_off);   // Rl
                MMA_BF16(&accR[nt*4], th0, th1, th2, th3, c0, c1);
            }
        }

        // ---- epilogue: sigmoid(edge) + res -> global
        {
            float* ob = out + (size_t)tile * 8192;
            #pragma unroll
            for (int nt = 0; nt < 8; ++nt) {
                const int col = nhalf * 64 + nt * 8 + cb;
                float o0 = 1.f / (1.f + __expf(-accE[nt*4+0])) + accR[nt*4+0];
                float o1 = 1.f / (1.f + __expf(-accE[nt*4+1])) + accR[nt*4+1];
                float o2 = 1.f / (1.f + __expf(-accE[nt*4+2])) + accR[nt*4+2];
                float o3 = 1.f / (1.f + __expf(-accE[nt*4+3])) + accR[nt*4+3];
                *(float2*)(ob + r0 * 128 + col)       = make_float2(o0, o1);
                *(float2*)(ob + (r0 + 8) * 128 + col) = make_float2(o2, o3);
            }
        }
    }
}

// ------------------------------------------------------------------ launch
extern "C" void kernel_launch(void* const* d_in, const int* in_sizes, int n_in,
                              void* d_out, int out_size)
{
    const float* t_ij = (const float*)d_in[0];
    const float* x1   = (const float*)d_in[1];
    const float* x2   = (const float*)d_in[2];
    const int*   nidx = (const int*)  d_in[3];
    const float* tq   = (const float*)d_in[4];
    const float* tk1  = (const float*)d_in[5];
    const float* tk2  = (const float*)d_in[6];
    const float* lnw  = (const float*)d_in[7];
    const float* ew   = (const float*)d_in[8];
    const float* rw   = (const float*)d_in[9];
    float* out = (float*)d_out;

    int dev = 0, nsm = 148;
    cudaGetDevice(&dev);
    cudaDeviceGetAttribute(&nsm, cudaDevAttrMultiProcessorCount, dev);

    cudaFuncSetAttribute(main_kernel, cudaFuncAttributeMaxDynamicSharedMemorySize, SMEM_B);

    wsplit_kernel<<<128, 256>>>(ew, rw);
    proj_kernel<<<NNODES, 128>>>(x1, x2, tq, tk1, tk2);
    main_kernel<<<nsm, 256, SMEM_B>>>(t_ij, nidx, lnw, out);
}

// round 5
// speedup vs baseline: 2.7749x; 1.0632x over previous
#include <cuda_runtime.h>
#include <cuda_bf16.h>
#include <cstdint>

#define NNODES 8192
#define QK_STRIDE 512
#define NTILES 4096          // node pairs

// ------------------------------------------------------------------ scratch
__device__ __align__(16) float g_q[(size_t)NNODES * QK_STRIDE];
__device__ __align__(16) float g_k[(size_t)NNODES * QK_STRIDE];
// 4 tile-blocked bf16 weight images, 32KB each: [edge_h][edge_l][res_h][res_l]
__device__ __align__(16) unsigned char g_wtiles[4 * 32768];

// ------------------------------------------------------------------ helpers
__device__ __forceinline__ uint32_t smem_u32(const void* p) {
    uint32_t a;
    asm("{ .reg .u64 t; cvta.to.shared.u64 t, %1; cvt.u32.u64 %0, t; }" : "=r"(a) : "l"(p));
    return a;
}
__device__ __forceinline__ uint32_t pack_bf16x2(float a, float b) {  // lo=bf16(a), hi=bf16(b)
    uint32_t p;
    asm("cvt.rn.bf16x2.f32 %0, %1, %2;" : "=r"(p) : "f"(b), "f"(a));
    return p;
}
#define LDSM_X4(r0, r1, r2, r3, addr) \
    asm volatile("ldmatrix.sync.aligned.m8n8.x4.shared.b16 {%0,%1,%2,%3}, [%4];" \
        : "=r"(r0), "=r"(r1), "=r"(r2), "=r"(r3) : "r"(addr))
#define LDSM_X2(r0, r1, addr) \
    asm volatile("ldmatrix.sync.aligned.m8n8.x2.shared.b16 {%0,%1}, [%2];" \
        : "=r"(r0), "=r"(r1) : "r"(addr))
#define MMA_BF16(c, a0, a1, a2, a3, b0, b1) \
    asm volatile("mma.sync.aligned.m16n8k16.row.col.f32.bf16.bf16.f32 " \
        "{%0,%1,%2,%3}, {%4,%5,%6,%7}, {%8,%9}, {%0,%1,%2,%3};" \
        : "+f"((c)[0]), "+f"((c)[1]), "+f"((c)[2]), "+f"((c)[3]) \
        : "r"(a0), "r"(a1), "r"(a2), "r"(a3), "r"(b0), "r"(b1))
#define CP_ASYNC16(saddr, gptr) \
    asm volatile("cp.async.cg.shared.global [%0], [%1], 16;" :: "r"(saddr), "l"(gptr))
#define CP_COMMIT() asm volatile("cp.async.commit_group;")
#define CP_WAIT0()  asm volatile("cp.async.wait_group 0;" ::: "memory")
#define CP_WAIT1()  asm volatile("cp.async.wait_group 1;" ::: "memory")

// ------------------------------------------------------------------ smem map (bytes)
#define SW_WT  0          // 131072: Eh,El,Rh,Rl (32KB each)
#define SW_WH  131072     // 16384
#define SW_WL  147456     // 16384
#define SW_KB0 163840     // 33024: 16 rows x 516 f32
#define SW_KB1 196864     // 33024
#define SW_Q   229888     // 2048 (one node's q)
#define SW_IDX 231936     // 256
#define SMEM_B 232192

// A-tile blocked offset (bytes): m in [0,64), k in [0,128)
__device__ __forceinline__ uint32_t a_off(int m, int k) {
    return (uint32_t)(((m >> 3) * 16 + (k >> 3)) * 128 + ((m & 7) << 4) + ((k & 7) << 1));
}

// ------------------------------------------------------------------ kernel 0: prep = wsplit + proj
__global__ void __launch_bounds__(256) prep_kernel(
    const float* __restrict__ ew,  const float* __restrict__ rw,
    const float* __restrict__ x1,  const float* __restrict__ x2,
    const float* __restrict__ tq,  const float* __restrict__ tk1,
    const float* __restrict__ tk2)
{
    const int tid = threadIdx.x;
    if (blockIdx.x < 128) {
        // ---- weight split
        int id = blockIdx.x * 256 + tid;              // 0..32767
        int w = id >> 14, k = (id >> 7) & 127, n = id & 127;
        float v = (w ? rw : ew)[k * 128 + n];         // B[n][k] = W[k][n]
        uint32_t ph = pack_bf16x2(v, 0.f);
        float hf = __uint_as_float(ph << 16);
        uint32_t pl = pack_bf16x2(v - hf, 0.f);
        uint32_t off = (uint32_t)(((n >> 3) * 8 + (k >> 4)) * 256 + (((k >> 3) & 1) << 7)
                                  + ((n & 7) << 4) + ((k & 7) << 1));
        *(uint16_t*)(g_wtiles + (size_t)(w * 2 + 0) * 32768 + off) = (uint16_t)(ph & 0xffffu);
        *(uint16_t*)(g_wtiles + (size_t)(w * 2 + 1) * 32768 + off) = (uint16_t)(pl & 0xffffu);
        return;
    }
    // ---- projections, 1 node/block, 4 groups of 64 threads
    __shared__ float sx[1024];
    const int node = blockIdx.x - 128;
    const float* px1 = x1 + (size_t)node * 384;
    const float* px2 = x2 + (size_t)node * 640;
    for (int i = tid; i < 1024; i += 256)
        sx[i] = (i < 384) ? __ldg(px1 + i) : __ldg(px2 + (i - 384));
    __syncthreads();

    const int grp = tid >> 6, e = tid & 63;
    if (grp < 2) {                    // q1 / k1  (ml=3)
        const float* W = grp ? tk1 : tq;
        float a0=0,a1=0,a2=0;
        #pragma unroll 8
        for (int d = 0; d < 128; ++d) {
            float w = __ldg(W + d * 64 + e);
            a0 += w*sx[d*3]; a1 += w*sx[d*3+1]; a2 += w*sx[d*3+2];
        }
        float* dst = (grp ? g_k : g_q) + (size_t)node * QK_STRIDE + e * 3;
        dst[0]=a0; dst[1]=a1; dst[2]=a2;
    } else {                          // q2 / k2  (ml=5)
        const float* W = (grp == 3) ? tk2 : tq;
        float a[5] = {0,0,0,0,0};
        #pragma unroll 4
        for (int d = 0; d < 128; ++d) {
            float w = __ldg(W + d * 64 + e);
            #pragma unroll
            for (int m = 0; m < 5; ++m) a[m] += w * sx[384 + d*5 + m];
        }
        float* dst = ((grp == 3) ? g_k : g_q) + (size_t)node * QK_STRIDE + 192 + e * 5;
        #pragma unroll
        for (int m = 0; m < 5; ++m) dst[m] = a[m];
    }
}

// ------------------------------------------------------------------ kernel 1: persistent fused main (512 thr)
__global__ void __launch_bounds__(512, 1) main_kernel(
    const float* __restrict__ t_ij, const int* __restrict__ nidx,
    const float* __restrict__ lnw, float* __restrict__ out)
{
    extern __shared__ char smem[];
    const uint32_t sb = smem_u32(smem);
    const int tid = threadIdx.x, lane = tid & 31, wid = tid >> 5;
    float* s_q = (float*)(smem + SW_Q);
    int*   s_ix = (int*)(smem + SW_IDX);

    // ---- stage split weights ONCE (128 KB)
    {
        const char* gsrc = (const char*)g_wtiles;
        #pragma unroll
        for (int i = 0; i < 16; ++i) {
            uint32_t off = (uint32_t)(i * 8192 + tid * 16);
            CP_ASYNC16(sb + SW_WT + off, gsrc + off);
        }
        CP_COMMIT();
    }
    const float gl0 = __ldg(lnw + 2 * lane), gl1 = __ldg(lnw + 2 * lane + 1);
    const float gl2 = __ldg(lnw + 64 + 2 * lane), gl3 = __ldg(lnw + 65 + 2 * lane);
    CP_WAIT0();
    __syncthreads();

    const int mbase = (wid & 3) * 16;      // M 4-way
    const int nquad = wid >> 2;            // N 4-way (32 cols each)
    const uint32_t a_thr = (uint32_t)(((mbase * 2 + 16 * ((lane >> 3) & 1) + (lane >> 4)) << 7)
                                      + ((lane & 7) << 4));
    const uint32_t b_thr = (uint32_t)(((((lane & 15) >> 3)) << 7) + ((lane & 7) << 4));
    const int r0  = mbase + (lane >> 2);       // frag row
    const int cbx = (lane & 3) * 2;            // frag col base

    for (int tile = blockIdx.x; tile < NTILES; tile += gridDim.x) {
        const int batch = tile >> 11;
        __syncthreads();                              // prev tile fully done
        if (tid < 64) s_ix[tid] = __ldg(nidx + tile * 64 + tid);
        __syncthreads();

        // ---- pipelined gather (cp.async, 2 buffers) + ip + LN
        #pragma unroll
        for (int it = 0; it < 4; ++it) {              // prologue: chunk 0
            int s = it * 512 + tid;
            int jj = s >> 7, part = s & 127;
            const char* src = (const char*)g_k
                + ((size_t)(batch * 4096 + s_ix[jj]) * 2048 + (size_t)part * 16);
            CP_ASYNC16(sb + SW_KB0 + (uint32_t)(jj * 2064 + part * 16), src);
        }
        CP_COMMIT();

        #pragma unroll
        for (int ch = 0; ch < 4; ++ch) {
            if (ch < 3) {
                const int nc = ch + 1;
                const uint32_t kb = (nc & 1) ? SW_KB1 : SW_KB0;
                #pragma unroll
                for (int it = 0; it < 4; ++it) {
                    int s = it * 512 + tid;
                    int jj = s >> 7, part = s & 127;
                    const char* src = (const char*)g_k
                        + ((size_t)(batch * 4096 + s_ix[nc * 16 + jj]) * 2048 + (size_t)part * 16);
                    CP_ASYNC16(sb + kb + (uint32_t)(jj * 2064 + part * 16), src);
                }
                CP_COMMIT();
            }
            if (!(ch & 1) && tid < 128)
                ((float4*)s_q)[tid] =
                    __ldg((const float4*)(g_q + (size_t)(tile * 2 + (ch >> 1)) * 512) + tid);
            if (ch < 3) CP_WAIT1(); else CP_WAIT0();
            __syncthreads();

            const float* kbuf = (const float*)(smem + ((ch & 1) ? SW_KB1 : SW_KB0));
            {
                const int r = wid;                 // one row per warp
                const float* kr = kbuf + r * 516;
                const int c0 = 2 * lane;
                int b = 3 * c0;
                float v0 = s_q[b]*kr[b] + s_q[b+1]*kr[b+1] + s_q[b+2]*kr[b+2];
                float v1 = s_q[b+3]*kr[b+3] + s_q[b+4]*kr[b+4] + s_q[b+5]*kr[b+5];
                int b2 = 192 + 10 * lane;
                float v2 = 0.f, v3 = 0.f;
                #pragma unroll
                for (int m5 = 0; m5 < 5; ++m5) {
                    v2 += s_q[b2+m5] * kr[b2+m5];
                    v3 += s_q[b2+5+m5] * kr[b2+5+m5];
                }
                float s  = v0+v1+v2+v3;
                float ss = v0*v0+v1*v1+v2*v2+v3*v3;
                #pragma unroll
                for (int o = 16; o > 0; o >>= 1) {
                    s  += __shfl_xor_sync(0xffffffffu, s,  o);
                    ss += __shfl_xor_sync(0xffffffffu, ss, o);
                }
                const float mu = s * (1.f/128.f);
                const float var = ss * (1.f/128.f) - mu*mu;
                const float sc = rsqrtf(fmaxf(var, 0.f) + 1e-5f);
                v0 = (v0-mu)*sc*gl0; v1 = (v1-mu)*sc*gl1;
                v2 = (v2-mu)*sc*gl2; v3 = (v3-mu)*sc*gl3;
                const int m = ch * 16 + r;
                uint32_t ph = pack_bf16x2(v0, v1);
                float h0 = __uint_as_float(ph << 16), h1 = __uint_as_float(ph & 0xffff0000u);
                uint32_t pl = pack_bf16x2(v0 - h0, v1 - h1);
                uint32_t off = a_off(m, c0);
                *(uint32_t*)(smem + SW_WH + off) = ph;
                *(uint32_t*)(smem + SW_WL + off) = pl;
                ph = pack_bf16x2(v2, v3);
                h0 = __uint_as_float(ph << 16); h1 = __uint_as_float(ph & 0xffff0000u);
                pl = pack_bf16x2(v2 - h0, v3 - h1);
                off = a_off(m, 64 + c0);
                *(uint32_t*)(smem + SW_WH + off) = ph;
                *(uint32_t*)(smem + SW_WL + off) = pl;
            }
            __syncthreads();
        }

        float accE[16], accR[16];
        #pragma unroll
        for (int i = 0; i < 16; ++i) { accE[i] = 0.f; accR[i] = 0.f; }

        // ---- edge GEMM (A = normalized W; frags reloaded per ks => low reg pressure)
        #pragma unroll
        for (int ks = 0; ks < 8; ++ks) {
            uint32_t a0, a1, a2, a3, l0, l1, l2, l3;
            LDSM_X4(a0, a1, a2, a3, sb + SW_WH + a_thr + (uint32_t)(ks * 256));
            LDSM_X4(l0, l1, l2, l3, sb + SW_WL + a_thr + (uint32_t)(ks * 256));
            #pragma unroll
            for (int nt = 0; nt < 4; ++nt) {
                const uint32_t tb_off = (uint32_t)((((nquad * 4 + nt) * 8 + ks)) << 8) + b_thr;
                uint32_t b0, b1, c0, c1;
                LDSM_X2(b0, b1, sb + SW_WT + tb_off);            // Eh
                MMA_BF16(&accE[nt*4], a0, a1, a2, a3, b0, b1);
                MMA_BF16(&accE[nt*4], l0, l1, l2, l3, b0, b1);
                LDSM_X2(c0, c1, sb + SW_WT + 32768u + tb_off);   // El
                MMA_BF16(&accE[nt*4], a0, a1, a2, a3, c0, c1);
            }
        }

        // ---- res GEMM (A = T straight from global, prefetched 1 ks ahead)
        {
            const float* tb = t_ij + (size_t)tile * 8192;
            float2 cur0 = __ldg((const float2*)(tb + r0 * 128 + cbx));
            float2 cur1 = __ldg((const float2*)(tb + (r0 + 8) * 128 + cbx));
            float2 cur2 = __ldg((const float2*)(tb + r0 * 128 + cbx + 8));
            float2 cur3 = __ldg((const float2*)(tb + (r0 + 8) * 128 + cbx + 8));
            #pragma unroll
            for (int ks = 0; ks < 8; ++ks) {
                float2 nx0, nx1, nx2, nx3;
                if (ks < 7) {
                    const int col = (ks + 1) * 16 + cbx;
                    nx0 = __ldg((const float2*)(tb + r0 * 128 + col));
                    nx1 = __ldg((const float2*)(tb + (r0 + 8) * 128 + col));
                    nx2 = __ldg((const float2*)(tb + r0 * 128 + col + 8));
                    nx3 = __ldg((const float2*)(tb + (r0 + 8) * 128 + col + 8));
                }
                uint32_t th0 = pack_bf16x2(cur0.x, cur0.y);
                uint32_t th1 = pack_bf16x2(cur1.x, cur1.y);
                uint32_t th2 = pack_bf16x2(cur2.x, cur2.y);
                uint32_t th3 = pack_bf16x2(cur3.x, cur3.y);
                uint32_t tl0 = pack_bf16x2(cur0.x - __uint_as_float(th0 << 16), cur0.y - __uint_as_float(th0 & 0xffff0000u));
                uint32_t tl1 = pack_bf16x2(cur1.x - __uint_as_float(th1 << 16), cur1.y - __uint_as_float(th1 & 0xffff0000u));
                uint32_t tl2 = pack_bf16x2(cur2.x - __uint_as_float(th2 << 16), cur2.y - __uint_as_float(th2 & 0xffff0000u));
                uint32_t tl3 = pack_bf16x2(cur3.x - __uint_as_float(th3 << 16), cur3.y - __uint_as_float(th3 & 0xffff0000u));
                #pragma unroll
                for (int nt = 0; nt < 4; ++nt) {
                    const uint32_t tb_off = (uint32_t)((((nquad * 4 + nt) * 8 + ks)) << 8) + b_thr;
                    uint32_t b0, b1, c0, c1;
                    LDSM_X2(b0, b1, sb + SW_WT + 65536u + tb_off);   // Rh
                    MMA_BF16(&accR[nt*4], th0, th1, th2, th3, b0, b1);
                    MMA_BF16(&accR[nt*4], tl0, tl1, tl2, tl3, b0, b1);
                    LDSM_X2(c0, c1, sb + SW_WT + 98304u + tb_off);   // Rl
                    MMA_BF16(&accR[nt*4], th0, th1, th2, th3, c0, c1);
                }
                cur0 = nx0; cur1 = nx1; cur2 = nx2; cur3 = nx3;
            }
        }

        // ---- epilogue: sigmoid(edge) + res -> global
        {
            float* ob = out + (size_t)tile * 8192;
            #pragma unroll
            for (int nt = 0; nt < 4; ++nt) {
                const int col = nquad * 32 + nt * 8 + cbx;
                float o0 = 1.f / (1.f + __expf(-accE[nt*4+0])) + accR[nt*4+0];
                float o1 = 1.f / (1.f + __expf(-accE[nt*4+1])) + accR[nt*4+1];
                float o2 = 1.f / (1.f + __expf(-accE[nt*4+2])) + accR[nt*4+2];
                float o3 = 1.f / (1.f + __expf(-accE[nt*4+3])) + accR[nt*4+3];
                *(float2*)(ob + r0 * 128 + col)       = make_float2(o0, o1);
                *(float2*)(ob + (r0 + 8) * 128 + col) = make_float2(o2, o3);
            }
        }
    }
}

// ------------------------------------------------------------------ launch
extern "C" void kernel_launch(void* const* d_in, const int* in_sizes, int n_in,
                              void* d_out, int out_size)
{
    const float* t_ij = (const float*)d_in[0];
    const float* x1   = (const float*)d_in[1];
    const float* x2   = (const float*)d_in[2];
    const int*   nidx = (const int*)  d_in[3];
    const float* tq   = (const float*)d_in[4];
    const float* tk1  = (const float*)d_in[5];
    const float* tk2  = (const float*)d_in[6];
    const float* lnw  = (const float*)d_in[7];
    const float* ew   = (const float*)d_in[8];
    const float* rw   = (const float*)d_in[9];
    float* out = (float*)d_out;

    int dev = 0, nsm = 148;
    cudaGetDevice(&dev);
    cudaDeviceGetAttribute(&nsm, cudaDevAttrMultiProcessorCount, dev);

    cudaFuncSetAttribute(main_kernel, cudaFuncAttributeMaxDynamicSharedMemorySize, SMEM_B);

    prep_kernel<<<128 + NNODES, 256>>>(ew, rw, x1, x2, tq, tk1, tk2);
    main_kernel<<<nsm, 512, SMEM_B>>>(t_ij, nidx, lnw, out);
}

// round 6
// speedup vs baseline: 2.8144x; 1.0142x over previous
#include <cuda_runtime.h>
#include <cuda_bf16.h>
#include <cstdint>

#define NNODES 8192
#define QK_STRIDE 512
#define NTILES 2048          // 4 nodes per tile

// ------------------------------------------------------------------ scratch
__device__ __align__(16) float g_q[(size_t)NNODES * QK_STRIDE];
__device__ __align__(16) float g_k[(size_t)NNODES * QK_STRIDE];
// 4 tile-blocked bf16 weight images, 32KB each: [edge_h][edge_l][res_h][res_l]
// off(n,k) = ((n>>3)*8 + (k>>4))*256 + ((k>>3)&1)*128 + (n&7)*16 + (k&7)*2
__device__ __align__(16) unsigned char g_wtiles[4 * 32768];

// ------------------------------------------------------------------ helpers
__device__ __forceinline__ uint32_t smem_u32(const void* p) {
    uint32_t a;
    asm("{ .reg .u64 t; cvta.to.shared.u64 t, %1; cvt.u32.u64 %0, t; }" : "=r"(a) : "l"(p));
    return a;
}
__device__ __forceinline__ uint32_t pack_bf16x2(float a, float b) {  // lo=bf16(a), hi=bf16(b)
    uint32_t p;
    asm("cvt.rn.bf16x2.f32 %0, %1, %2;" : "=r"(p) : "f"(b), "f"(a));
    return p;
}
#define LDSM_X4(r0, r1, r2, r3, addr) \
    asm volatile("ldmatrix.sync.aligned.m8n8.x4.shared.b16 {%0,%1,%2,%3}, [%4];" \
        : "=r"(r0), "=r"(r1), "=r"(r2), "=r"(r3) : "r"(addr))
#define MMA_BF16(c, a0, a1, a2, a3, b0, b1) \
    asm volatile("mma.sync.aligned.m16n8k16.row.col.f32.bf16.bf16.f32 " \
        "{%0,%1,%2,%3}, {%4,%5,%6,%7}, {%8,%9}, {%0,%1,%2,%3};" \
        : "+f"((c)[0]), "+f"((c)[1]), "+f"((c)[2]), "+f"((c)[3]) \
        : "r"(a0), "r"(a1), "r"(a2), "r"(a3), "r"(b0), "r"(b1))
#define CP_ASYNC16(saddr, gptr) \
    asm volatile("cp.async.cg.shared.global [%0], [%1], 16;" :: "r"(saddr), "l"(gptr))
#define CP_COMMIT() asm volatile("cp.async.commit_group;")
#define CP_WAIT0()  asm volatile("cp.async.wait_group 0;" ::: "memory")

// ------------------------------------------------------------------ main smem map (bytes)
#define SW_WT  0          // 131072: Eh,El,Rh,Rl (32KB each)
#define SW_WH  131072     // 32768: normalized W hi (M=128)
#define SW_WL  163840     // 32768: W lo
#define SW_KB0 196608     // 16512: 8 rows x 516 f32
#define SW_KB1 213120     // 16512
#define SW_IDX 229632     // 512
#define SMEM_B 230144

// prep smem: [0:98304) weights tq|tk1|tk2 fp32, [98304:...) x slots 8 x 1040 f32
#define PREP_SMEM (98304 + 8 * 1040 * 4)

// ------------------------------------------------------------------ kernel 0: prep = wsplit + proj
__global__ void __launch_bounds__(256) prep_kernel(
    const float* __restrict__ ew,  const float* __restrict__ rw,
    const float* __restrict__ x1,  const float* __restrict__ x2,
    const float* __restrict__ tq,  const float* __restrict__ tk1,
    const float* __restrict__ tk2)
{
    extern __shared__ char smem[];
    const int tid = threadIdx.x;
    if (blockIdx.x < 128) {
        // ---- weight split (edge/res GEMM B images)
        int id = blockIdx.x * 256 + tid;              // 0..32767
        int w = id >> 14, k = (id >> 7) & 127, n = id & 127;
        float v = (w ? rw : ew)[k * 128 + n];         // B[n][k] = W[k][n]
        uint32_t ph = pack_bf16x2(v, 0.f);
        float hf = __uint_as_float(ph << 16);
        uint32_t pl = pack_bf16x2(v - hf, 0.f);
        uint32_t off = (uint32_t)(((n >> 3) * 8 + (k >> 4)) * 256 + (((k >> 3) & 1) << 7)
                                  + ((n & 7) << 4) + ((k & 7) << 1));
        *(uint16_t*)(g_wtiles + (size_t)(w * 2 + 0) * 32768 + off) = (uint16_t)(ph & 0xffffu);
        *(uint16_t*)(g_wtiles + (size_t)(w * 2 + 1) * 32768 + off) = (uint16_t)(pl & 0xffffu);
        return;
    }
    // ---- projections: 32 nodes per block, weights staged once in smem
    float* psm = (float*)smem;
    const uint32_t sb = smem_u32(smem);
    {
        #pragma unroll
        for (int i = 0; i < 8; ++i) {
            uint32_t off = (uint32_t)(i * 4096 + tid * 16);
            CP_ASYNC16(sb + off,           (const char*)tq  + off);
            CP_ASYNC16(sb + 32768u + off,  (const char*)tk1 + off);
            CP_ASYNC16(sb + 65536u + off,  (const char*)tk2 + off);
        }
        CP_COMMIT();
    }
    const int wid = tid >> 5, lane = tid & 31;
    float* sx = psm + 24576 + wid * 1040;     // this warp's x staging [d*8+m]
    const int nbase = (blockIdx.x - 128) * 32;
    CP_WAIT0();
    __syncthreads();

    const float2* wqp  = (const float2*)psm + lane;            // [d][e-pair]
    const float2* wk1p = (const float2*)(psm + 8192) + lane;
    const float2* wk2p = (const float2*)(psm + 16384) + lane;

    for (int it = 0; it < 4; ++it) {
        const int node = nbase + it * 8 + wid;
        const float* px1 = x1 + (size_t)node * 384;
        const float* px2 = x2 + (size_t)node * 640;
        for (int j = lane; j < 384; j += 32) { int d = j / 3; sx[d * 8 + (j - d * 3)] = __ldg(px1 + j); }
        for (int j = lane; j < 640; j += 32) { int d = j / 5; sx[d * 8 + 3 + (j - d * 5)] = __ldg(px2 + j); }
        __syncwarp();

        float aq[16], ak[16];   // [m][e0/e1]
        #pragma unroll
        for (int i = 0; i < 16; ++i) { aq[i] = 0.f; ak[i] = 0.f; }
        #pragma unroll 4
        for (int d = 0; d < 128; ++d) {
            const float2 w_q = wqp[d * 32];
            const float2 w_1 = wk1p[d * 32];
            const float2 w_2 = wk2p[d * 32];
            const float2* xr = (const float2*)(sx + d * 8);
            float2 x01 = xr[0], x23 = xr[1], x45 = xr[2], x67 = xr[3];
            const float xs[8] = {x01.x, x01.y, x23.x, x23.y, x45.x, x45.y, x67.x, x67.y};
            #pragma unroll
            for (int m = 0; m < 8; ++m) {
                aq[m * 2]     += w_q.x * xs[m];
                aq[m * 2 + 1] += w_q.y * xs[m];
                const float wk0 = (m < 3) ? w_1.x : w_2.x;
                const float wk1v = (m < 3) ? w_1.y : w_2.y;
                ak[m * 2]     += wk0 * xs[m];
                ak[m * 2 + 1] += wk1v * xs[m];
            }
        }
        float* oq = g_q + (size_t)node * QK_STRIDE;
        float* ok = g_k + (size_t)node * QK_STRIDE;
        #pragma unroll
        for (int m = 0; m < 3; ++m) {
            oq[6 * lane + m]     = aq[m * 2];
            oq[6 * lane + 3 + m] = aq[m * 2 + 1];
            ok[6 * lane + m]     = ak[m * 2];
            ok[6 * lane + 3 + m] = ak[m * 2 + 1];
        }
        #pragma unroll
        for (int m = 3; m < 8; ++m) {
            oq[192 + 10 * lane + (m - 3)]     = aq[m * 2];
            oq[192 + 10 * lane + 5 + (m - 3)] = aq[m * 2 + 1];
            ok[192 + 10 * lane + (m - 3)]     = ak[m * 2];
            ok[192 + 10 * lane + 5 + (m - 3)] = ak[m * 2 + 1];
        }
        __syncwarp();
    }
}

// ------------------------------------------------------------------ kernel 1: persistent fused main (512 thr)
__global__ void __launch_bounds__(512, 1) main_kernel(
    const float* __restrict__ t_ij, const int* __restrict__ nidx,
    const float* __restrict__ lnw, float* __restrict__ out)
{
    extern __shared__ char smem[];
    const uint32_t sb = smem_u32(smem);
    const int tid = threadIdx.x, lane = tid & 31, wid = tid >> 5;
    int* s_ix = (int*)(smem + SW_IDX);

    // ---- stage split GEMM weights ONCE (128 KB)
    {
        const char* gsrc = (const char*)g_wtiles;
        #pragma unroll
        for (int i = 0; i < 16; ++i) {
            uint32_t off = (uint32_t)(i * 8192 + tid * 16);
            CP_ASYNC16(sb + SW_WT + off, gsrc + off);
        }
        CP_COMMIT();
    }
    const float gl0 = __ldg(lnw + 2 * lane), gl1 = __ldg(lnw + 2 * lane + 1);
    const float gl2 = __ldg(lnw + 64 + 2 * lane), gl3 = __ldg(lnw + 65 + 2 * lane);
    CP_WAIT0();
    __syncthreads();

    const int wq = wid & 3, nq = wid >> 2;
    const uint32_t a_lane = (uint32_t)((((lane >> 3) & 1) << 11) + ((lane >> 4) << 7) + ((lane & 7) << 4));
    const uint32_t b_lane = (uint32_t)(((lane >> 4) << 11) + (((lane >> 3) & 1) << 7) + ((lane & 7) << 4));
    const int r0  = wq * 32 + (lane >> 2);
    const int cbx = (lane & 3) * 2;
    const bool producer = (wid >= 8);
    const int ptid = tid - 256;

    float q3[6], q5[10];

    for (int tile = blockIdx.x; tile < NTILES; tile += gridDim.x) {
        const int batch = tile >> 10;
        __syncthreads();                              // prev tile fully done
        if (tid < 128) s_ix[tid] = __ldg(nidx + tile * 128 + tid);
        __syncthreads();

        // prologue: producers issue chunk 0
        if (producer) {
            #pragma unroll
            for (int it = 0; it < 4; ++it) {
                int s = it * 256 + ptid;
                int jj = s >> 7, part = s & 127;
                const char* src = (const char*)g_k
                    + ((size_t)(batch * 4096 + s_ix[jj]) * 2048 + (size_t)part * 16);
                CP_ASYNC16(sb + SW_KB0 + (uint32_t)(jj * 2064 + part * 16), src);
            }
            CP_COMMIT();
        }

        for (int ch = 0; ch < 16; ++ch) {
            if (producer) CP_WAIT0();
            __syncthreads();                          // publish buf[ch&1]; prev compute done
            if (producer) {
                if (ch < 15) {
                    const uint32_t kb = ((ch + 1) & 1) ? SW_KB1 : SW_KB0;
                    const int ib = (ch + 1) * 8;
                    #pragma unroll
                    for (int it = 0; it < 4; ++it) {
                        int s = it * 256 + ptid;
                        int jj = s >> 7, part = s & 127;
                        const char* src = (const char*)g_k
                            + ((size_t)(batch * 4096 + s_ix[ib + jj]) * 2048 + (size_t)part * 16);
                        CP_ASYNC16(sb + kb + (uint32_t)(jj * 2064 + part * 16), src);
                    }
                    CP_COMMIT();
                }
            } else {
                // compute warp: row wid of chunk ch
                if ((ch & 3) == 0) {
                    const float* qp = g_q + (size_t)(tile * 4 + (ch >> 2)) * 512;
                    const float2* qa = (const float2*)(qp + 6 * lane);
                    float2 t0 = __ldg(qa), t1 = __ldg(qa + 1), t2 = __ldg(qa + 2);
                    q3[0] = t0.x; q3[1] = t0.y; q3[2] = t1.x; q3[3] = t1.y; q3[4] = t2.x; q3[5] = t2.y;
                    const float2* qb = (const float2*)(qp + 192 + 10 * lane);
                    float2 u0 = __ldg(qb), u1 = __ldg(qb + 1), u2 = __ldg(qb + 2), u3 = __ldg(qb + 3), u4 = __ldg(qb + 4);
                    q5[0] = u0.x; q5[1] = u0.y; q5[2] = u1.x; q5[3] = u1.y; q5[4] = u2.x;
                    q5[5] = u2.y; q5[6] = u3.x; q5[7] = u3.y; q5[8] = u4.x; q5[9] = u4.y;
                }
                const float* kr = (const float*)(smem + ((ch & 1) ? SW_KB1 : SW_KB0)) + wid * 516;
                const int b = 6 * lane;
                float v0 = q3[0]*kr[b] + q3[1]*kr[b+1] + q3[2]*kr[b+2];
                float v1 = q3[3]*kr[b+3] + q3[4]*kr[b+4] + q3[5]*kr[b+5];
                const int b2 = 192 + 10 * lane;
                float v2 = 0.f, v3 = 0.f;
                #pragma unroll
                for (int m5 = 0; m5 < 5; ++m5) {
                    v2 += q5[m5] * kr[b2 + m5];
                    v3 += q5[5 + m5] * kr[b2 + 5 + m5];
                }
                float s  = v0 + v1 + v2 + v3;
                float ss = v0*v0 + v1*v1 + v2*v2 + v3*v3;
                #pragma unroll
                for (int o = 16; o > 0; o >>= 1) {
                    s  += __shfl_xor_sync(0xffffffffu, s,  o);
                    ss += __shfl_xor_sync(0xffffffffu, ss, o);
                }
                const float mu = s * (1.f / 128.f);
                const float var = ss * (1.f / 128.f) - mu * mu;
                const float sc = rsqrtf(fmaxf(var, 0.f) + 1e-5f);
                v0 = (v0 - mu) * sc * gl0; v1 = (v1 - mu) * sc * gl1;
                v2 = (v2 - mu) * sc * gl2; v3 = (v3 - mu) * sc * gl3;
                const int m = ch * 8 + wid;
                const uint32_t rowb = (uint32_t)(((m >> 3) * 16) * 128 + (m & 7) * 16);
                const uint32_t off1 = rowb + (uint32_t)((lane >> 2) * 128 + (lane & 3) * 4);
                const uint32_t off2 = off1 + 8u * 128u;
                uint32_t ph = pack_bf16x2(v0, v1);
                float h0 = __uint_as_float(ph << 16), h1 = __uint_as_float(ph & 0xffff0000u);
                uint32_t pl = pack_bf16x2(v0 - h0, v1 - h1);
                *(uint32_t*)(smem + SW_WH + off1) = ph;
                *(uint32_t*)(smem + SW_WL + off1) = pl;
                ph = pack_bf16x2(v2, v3);
                h0 = __uint_as_float(ph << 16); h1 = __uint_as_float(ph & 0xffff0000u);
                pl = pack_bf16x2(v2 - h0, v3 - h1);
                *(uint32_t*)(smem + SW_WH + off2) = ph;
                *(uint32_t*)(smem + SW_WL + off2) = pl;
            }
        }
        __syncthreads();   // last chunk's W writes visible

        float accE[32], accR[32];
        #pragma unroll
        for (int i = 0; i < 32; ++i) { accE[i] = 0.f; accR[i] = 0.f; }

        // ---- edge GEMM: A = normalized W (smem), B = Eh/El
        #pragma unroll
        for (int ks = 0; ks < 8; ++ks) {
            uint32_t ah[8], al[8];
            const uint32_t aoff = a_lane + (uint32_t)(ks * 256);
            LDSM_X4(ah[0], ah[1], ah[2], ah[3], sb + SW_WH + (uint32_t)((4 * wq) * 2048) + aoff);
            LDSM_X4(ah[4], ah[5], ah[6], ah[7], sb + SW_WH + (uint32_t)((4 * wq + 2) * 2048) + aoff);
            LDSM_X4(al[0], al[1], al[2], al[3], sb + SW_WL + (uint32_t)((4 * wq) * 2048) + aoff);
            LDSM_X4(al[4], al[5], al[6], al[7], sb + SW_WL + (uint32_t)((4 * wq + 2) * 2048) + aoff);
            #pragma unroll
            for (int ntp = 0; ntp < 2; ++ntp) {
                const uint32_t boff = (uint32_t)((nq * 4 + ntp * 2) * 2048) + b_lane + (uint32_t)(ks * 256);
                uint32_t e0, e1, e2, e3, f0, f1, f2, f3;
                LDSM_X4(e0, e1, e2, e3, sb + SW_WT + boff);
                MMA_BF16(&accE[(0 + ntp * 2 + 0) * 4], ah[0], ah[1], ah[2], ah[3], e0, e1);
                MMA_BF16(&accE[(0 + ntp * 2 + 1) * 4], ah[0], ah[1], ah[2], ah[3], e2, e3);
                MMA_BF16(&accE[(4 + ntp * 2 + 0) * 4], ah[4], ah[5], ah[6], ah[7], e0, e1);
                MMA_BF16(&accE[(4 + ntp * 2 + 1) * 4], ah[4], ah[5], ah[6], ah[7], e2, e3);
                MMA_BF16(&accE[(0 + ntp * 2 + 0) * 4], al[0], al[1], al[2], al[3], e0, e1);
                MMA_BF16(&accE[(0 + ntp * 2 + 1) * 4], al[0], al[1], al[2], al[3], e2, e3);
                MMA_BF16(&accE[(4 + ntp * 2 + 0) * 4], al[4], al[5], al[6], al[7], e0, e1);
                MMA_BF16(&accE[(4 + ntp * 2 + 1) * 4], al[4], al[5], al[6], al[7], e2, e3);
                LDSM_X4(f0, f1, f2, f3, sb + SW_WT + 32768u + boff);
                MMA_BF16(&accE[(0 + ntp * 2 + 0) * 4], ah[0], ah[1], ah[2], ah[3], f0, f1);
                MMA_BF16(&accE[(0 + ntp * 2 + 1) * 4], ah[0], ah[1], ah[2], ah[3], f2, f3);
                MMA_BF16(&accE[(4 + ntp * 2 + 0) * 4], ah[4], ah[5], ah[6], ah[7], f0, f1);
                MMA_BF16(&accE[(4 + ntp * 2 + 1) * 4], ah[4], ah[5], ah[6], ah[7], f2, f3);
            }
        }

        // ---- res GEMM: A = T from global (hi/lo split in regs), B = Rh/Rl
        {
            const float* tb = t_ij + (size_t)tile * 16384;
            #pragma unroll
            for (int ks = 0; ks < 8; ++ks) {
                uint32_t th[8], tl[8];
                const int col = ks * 16 + cbx;
                #pragma unroll
                for (int sub = 0; sub < 2; ++sub) {
                    const int rr = r0 + sub * 16;
                    float2 v0 = __ldg((const float2*)(tb + rr * 128 + col));
                    float2 v1 = __ldg((const float2*)(tb + (rr + 8) * 128 + col));
                    float2 v2 = __ldg((const float2*)(tb + rr * 128 + col + 8));
                    float2 v3 = __ldg((const float2*)(tb + (rr + 8) * 128 + col + 8));
                    uint32_t p0 = pack_bf16x2(v0.x, v0.y);
                    uint32_t p1 = pack_bf16x2(v1.x, v1.y);
                    uint32_t p2 = pack_bf16x2(v2.x, v2.y);
                    uint32_t p3 = pack_bf16x2(v3.x, v3.y);
                    th[sub * 4 + 0] = p0; th[sub * 4 + 1] = p1; th[sub * 4 + 2] = p2; th[sub * 4 + 3] = p3;
                    tl[sub * 4 + 0] = pack_bf16x2(v0.x - __uint_as_float(p0 << 16), v0.y - __uint_as_float(p0 & 0xffff0000u));
                    tl[sub * 4 + 1] = pack_bf16x2(v1.x - __uint_as_float(p1 << 16), v1.y - __uint_as_float(p1 & 0xffff0000u));
                    tl[sub * 4 + 2] = pack_bf16x2(v2.x - __uint_as_float(p2 << 16), v2.y - __uint_as_float(p2 & 0xffff0000u));
                    tl[sub * 4 + 3] = pack_bf16x2(v3.x - __uint_as_float(p3 << 16), v3.y - __uint_as_float(p3 & 0xffff0000u));
                }
                #pragma unroll
                for (int ntp = 0; ntp < 2; ++ntp) {
                    const uint32_t boff = (uint32_t)((nq * 4 + ntp * 2) * 2048) + b_lane + (uint32_t)(ks * 256);
                    uint32_t b0, b1, b2, b3, c0, c1, c2, c3;
                    LDSM_X4(b0, b1, b2, b3, sb + SW_WT + 65536u + boff);
                    MMA_BF16(&accR[(0 + ntp * 2 + 0) * 4], th[0], th[1], th[2], th[3], b0, b1);
                    MMA_BF16(&accR[(0 + ntp * 2 + 1) * 4], th[0], th[1], th[2], th[3], b2, b3);
                    MMA_BF16(&accR[(4 + ntp * 2 + 0) * 4], th[4], th[5], th[6], th[7], b0, b1);
                    MMA_BF16(&accR[(4 + ntp * 2 + 1) * 4], th[4], th[5], th[6], th[7], b2, b3);
                    MMA_BF16(&accR[(0 + ntp * 2 + 0) * 4], tl[0], tl[1], tl[2], tl[3], b0, b1);
                    MMA_BF16(&accR[(0 + ntp * 2 + 1) * 4], tl[0], tl[1], tl[2], tl[3], b2, b3);
                    MMA_BF16(&accR[(4 + ntp * 2 + 0) * 4], tl[4], tl[5], tl[6], tl[7], b0, b1);
                    MMA_BF16(&accR[(4 + ntp * 2 + 1) * 4], tl[4], tl[5], tl[6], tl[7], b2, b3);
                    LDSM_X4(c0, c1, c2, c3, sb + SW_WT + 98304u + boff);
                    MMA_BF16(&accR[(0 + ntp * 2 + 0) * 4], th[0], th[1], th[2], th[3], c0, c1);
                    MMA_BF16(&accR[(0 + ntp * 2 + 1) * 4], th[0], th[1], th[2], th[3], c2, c3);
                    MMA_BF16(&accR[(4 + ntp * 2 + 0) * 4], th[4], th[5], th[6], th[7], c0, c1);
                    MMA_BF16(&accR[(4 + ntp * 2 + 1) * 4], th[4], th[5], th[6], th[7], c2, c3);
                }
            }
        }

        // ---- epilogue: sigmoid(edge) + res -> global
        {
            float* ob = out + (size_t)tile * 16384;
            #pragma unroll
            for (int sub = 0; sub < 2; ++sub) {
                const int rr = r0 + sub * 16;
                #pragma unroll
                for (int nt = 0; nt < 4; ++nt) {
                    const int idx = (sub * 4 + nt) * 4;
                    const int colo = nq * 32 + nt * 8 + cbx;
                    float o0 = 1.f / (1.f + __expf(-accE[idx + 0])) + accR[idx + 0];
                    float o1 = 1.f / (1.f + __expf(-accE[idx + 1])) + accR[idx + 1];
                    float o2 = 1.f / (1.f + __expf(-accE[idx + 2])) + accR[idx + 2];
                    float o3 = 1.f / (1.f + __expf(-accE[idx + 3])) + accR[idx + 3];
                    *(float2*)(ob + rr * 128 + colo)       = make_float2(o0, o1);
                    *(float2*)(ob + (rr + 8) * 128 + colo) = make_float2(o2, o3);
                }
            }
        }
    }
}

// ------------------------------------------------------------------ launch
extern "C" void kernel_launch(void* const* d_in, const int* in_sizes, int n_in,
                              void* d_out, int out_size)
{
    const float* t_ij = (const float*)d_in[0];
    const float* x1   = (const float*)d_in[1];
    const float* x2   = (const float*)d_in[2];
    const int*   nidx = (const int*)  d_in[3];
    const float* tq   = (const float*)d_in[4];
    const float* tk1  = (const float*)d_in[5];
    const float* tk2  = (const float*)d_in[6];
    const float* lnw  = (const float*)d_in[7];
    const float* ew   = (const float*)d_in[8];
    const float* rw   = (const float*)d_in[9];
    float* out = (float*)d_out;

    int dev = 0, nsm = 148;
    cudaGetDevice(&dev);
    cudaDeviceGetAttribute(&nsm, cudaDevAttrMultiProcessorCount, dev);

    cudaFuncSetAttribute(prep_kernel, cudaFuncAttributeMaxDynamicSharedMemorySize, PREP_SMEM);
    cudaFuncSetAttribute(main_kernel, cudaFuncAttributeMaxDynamicSharedMemorySize, SMEM_B);

    prep_kernel<<<128 + NNODES / 32, 256, PREP_SMEM>>>(ew, rw, x1, x2, tq, tk1, tk2);
    main_kernel<<<nsm, 512, SMEM_B>>>(t_ij, nidx, lnw, out);
}

// round 9
// speedup vs baseline: 3.4582x; 1.2288x over previous
#include <cuda_runtime.h>
#include <cuda_bf16.h>
#include <cstdint>

#define NNODES 8192
#define QK_STRIDE 512
#define NT_TOTAL 2048        // 4 nodes per tile (M=128)

// ------------------------------------------------------------------ scratch
__device__ __align__(16) float g_q[(size_t)NNODES * QK_STRIDE];
__device__ __align__(16) float g_k[(size_t)NNODES * QK_STRIDE];
// 3 tile-blocked weight images, 32KB each: [E fp16][Rh bf16][Rl bf16]
// off(n,k) = ((n>>3)*8 + (k>>4))*256 + ((k>>3)&1)*128 + (n&7)*16 + (k&7)*2
__device__ __align__(16) unsigned char g_wtiles[3 * 32768];

// ------------------------------------------------------------------ helpers
__device__ __forceinline__ uint32_t smem_u32(const void* p) {
    uint32_t a;
    asm("{ .reg .u64 t; cvta.to.shared.u64 t, %1; cvt.u32.u64 %0, t; }" : "=r"(a) : "l"(p));
    return a;
}
__device__ __forceinline__ uint32_t pack_bf16x2(float a, float b) {  // lo=bf16(a), hi=bf16(b)
    uint32_t p;
    asm("cvt.rn.bf16x2.f32 %0, %1, %2;" : "=r"(p) : "f"(b), "f"(a));
    return p;
}
__device__ __forceinline__ uint32_t pack_f16x2(float a, float b) {   // lo=f16(a), hi=f16(b)
    uint32_t p;
    asm("cvt.rn.f16x2.f32 %0, %1, %2;" : "=r"(p) : "f"(b), "f"(a));
    return p;
}
#define LDSM_X4(r0, r1, r2, r3, addr) \
    asm volatile("ldmatrix.sync.aligned.m8n8.x4.shared.b16 {%0,%1,%2,%3}, [%4];" \
        : "=r"(r0), "=r"(r1), "=r"(r2), "=r"(r3) : "r"(addr))
#define MMA_BF16(c, a0, a1, a2, a3, b0, b1) \
    asm volatile("mma.sync.aligned.m16n8k16.row.col.f32.bf16.bf16.f32 " \
        "{%0,%1,%2,%3}, {%4,%5,%6,%7}, {%8,%9}, {%0,%1,%2,%3};" \
        : "+f"((c)[0]), "+f"((c)[1]), "+f"((c)[2]), "+f"((c)[3]) \
        : "r"(a0), "r"(a1), "r"(a2), "r"(a3), "r"(b0), "r"(b1))
#define MMA_F16(c, a0, a1, a2, a3, b0, b1) \
    asm volatile("mma.sync.aligned.m16n8k16.row.col.f32.f16.f16.f32 " \
        "{%0,%1,%2,%3}, {%4,%5,%6,%7}, {%8,%9}, {%0,%1,%2,%3};" \
        : "+f"((c)[0]), "+f"((c)[1]), "+f"((c)[2]), "+f"((c)[3]) \
        : "r"(a0), "r"(a1), "r"(a2), "r"(a3), "r"(b0), "r"(b1))
#define CP_ASYNC16(saddr, gptr) \
    asm volatile("cp.async.cg.shared.global [%0], [%1], 16;" :: "r"(saddr), "l"(gptr))
#define CP_COMMIT() asm volatile("cp.async.commit_group;")
#define CP_WAIT0()  asm volatile("cp.async.wait_group 0;" ::: "memory")
#define CP_WAIT1()  asm volatile("cp.async.wait_group 1;" ::: "memory")
#define NB_LN()     asm volatile("bar.sync 1, 256;" ::: "memory")

// ------------------------------------------------------------------ main smem map (bytes)
#define SW_E   0          // 32768 fp16 edge image
#define SW_RH  32768      // 32768 bf16 res hi
#define SW_RL  65536      // 32768 bf16 res lo
#define SW_W0  98304      // 32768 fp16 W buf 0 (M=128)
#define SW_W1  131072     // 32768 fp16 W buf 1
#define SW_KB0 163840     // 16512: 8 rows x 516 f32
#define SW_KB1 180352     // 16512
#define SW_IDX 196864     // 512
#define SMEM_B 197376

// prep smem: [0:98304) weights tq|tk1|tk2 fp32, then x slots 8 x 1040 f32
#define PREP_SMEM (98304 + 8 * 1040 * 4)

// ------------------------------------------------------------------ kernel 0: prep = wsplit + proj
__global__ void __launch_bounds__(256) prep_kernel(
    const float* __restrict__ ew,  const float* __restrict__ rw,
    const float* __restrict__ x1,  const float* __restrict__ x2,
    const float* __restrict__ tq,  const float* __restrict__ tk1,
    const float* __restrict__ tk2)
{
    extern __shared__ char smem[];
    const int tid = threadIdx.x;
    if (blockIdx.x < 128) {
        int id = blockIdx.x * 256 + tid;              // 0..32767
        int w = id >> 14, k = (id >> 7) & 127, n = id & 127;
        float v = (w ? rw : ew)[k * 128 + n];         // B[n][k] = W[k][n]
        uint32_t off = (uint32_t)(((n >> 3) * 8 + (k >> 4)) * 256 + (((k >> 3) & 1) << 7)
                                  + ((n & 7) << 4) + ((k & 7) << 1));
        if (w == 0) {
            uint32_t p = pack_f16x2(v, 0.f);
            *(uint16_t*)(g_wtiles + off) = (uint16_t)(p & 0xffffu);
        } else {
            uint32_t ph = pack_bf16x2(v, 0.f);
            float hf = __uint_as_float(ph << 16);
            uint32_t pl = pack_bf16x2(v - hf, 0.f);
            *(uint16_t*)(g_wtiles + 32768u + off) = (uint16_t)(ph & 0xffffu);
            *(uint16_t*)(g_wtiles + 65536u + off) = (uint16_t)(pl & 0xffffu);
        }
        return;
    }
    // ---- projections: 32 nodes per block
    float* psm = (float*)smem;
    const uint32_t sb = smem_u32(smem);
    {
        #pragma unroll
        for (int i = 0; i < 8; ++i) {
            uint32_t off = (uint32_t)(i * 4096 + tid * 16);
            CP_ASYNC16(sb + off,           (const char*)tq  + off);
            CP_ASYNC16(sb + 32768u + off,  (const char*)tk1 + off);
            CP_ASYNC16(sb + 65536u + off,  (const char*)tk2 + off);
        }
        CP_COMMIT();
    }
    const int wid = tid >> 5, lane = tid & 31;
    float* sx = psm + 24576 + wid * 1040;
    const int nbase = (blockIdx.x - 128) * 32;
    CP_WAIT0();
    __syncthreads();

    const float2* wqp  = (const float2*)psm + lane;
    const float2* wk1p = (const float2*)(psm + 8192) + lane;
    const float2* wk2p = (const float2*)(psm + 16384) + lane;

    for (int it = 0; it < 4; ++it) {
        const int node = nbase + it * 8 + wid;
        const float* px1 = x1 + (size_t)node * 384;
        const float* px2 = x2 + (size_t)node * 640;
        for (int j = lane; j < 384; j += 32) { int d = j / 3; sx[d * 8 + (j - d * 3)] = __ldg(px1 + j); }
        for (int j = lane; j < 640; j += 32) { int d = j / 5; sx[d * 8 + 3 + (j - d * 5)] = __ldg(px2 + j); }
        __syncwarp();

        float aq[16], ak[16];
        #pragma unroll
        for (int i = 0; i < 16; ++i) { aq[i] = 0.f; ak[i] = 0.f; }
        #pragma unroll 4
        for (int d = 0; d < 128; ++d) {
            const float2 w_q = wqp[d * 32];
            const float2 w_1 = wk1p[d * 32];
            const float2 w_2 = wk2p[d * 32];
            const float2* xr = (const float2*)(sx + d * 8);
            float2 x01 = xr[0], x23 = xr[1], x45 = xr[2], x67 = xr[3];
            const float xs[8] = {x01.x, x01.y, x23.x, x23.y, x45.x, x45.y, x67.x, x67.y};
            #pragma unroll
            for (int m = 0; m < 8; ++m) {
                aq[m * 2]     += w_q.x * xs[m];
                aq[m * 2 + 1] += w_q.y * xs[m];
                const float wk0  = (m < 3) ? w_1.x : w_2.x;
                const float wk1v = (m < 3) ? w_1.y : w_2.y;
                ak[m * 2]     += wk0  * xs[m];
                ak[m * 2 + 1] += wk1v * xs[m];
            }
        }
        float* oq = g_q + (size_t)node * QK_STRIDE;
        float* ok = g_k + (size_t)node * QK_STRIDE;
        #pragma unroll
        for (int m = 0; m < 3; ++m) {
            oq[6 * lane + m]     = aq[m * 2];
            oq[6 * lane + 3 + m] = aq[m * 2 + 1];
            ok[6 * lane + m]     = ak[m * 2];
            ok[6 * lane + 3 + m] = ak[m * 2 + 1];
        }
        #pragma unroll
        for (int m = 3; m < 8; ++m) {
            oq[192 + 10 * lane + (m - 3)]     = aq[m * 2];
            oq[192 + 10 * lane + 5 + (m - 3)] = aq[m * 2 + 1];
            ok[192 + 10 * lane + (m - 3)]     = ak[m * 2];
            ok[192 + 10 * lane + 5 + (m - 3)] = ak[m * 2 + 1];
        }
        __syncwarp();
    }
}

// ------------------------------------------------------------------ kernel 1: warp-specialized persistent main
__global__ void __launch_bounds__(512, 1) main_kernel(
    const float* __restrict__ t_ij, const int* __restrict__ nidx,
    const float* __restrict__ lnw, float* __restrict__ out)
{
    extern __shared__ char smem[];
    const uint32_t sb = smem_u32(smem);
    const int tid = threadIdx.x, lane = tid & 31, wid = tid >> 5;
    int* s_ix = (int*)(smem + SW_IDX);

    // ---- stage weight images ONCE (96 KB)
    {
        const char* gsrc = (const char*)g_wtiles;
        #pragma unroll
        for (int i = 0; i < 12; ++i) {
            uint32_t off = (uint32_t)(i * 8192 + tid * 16);
            CP_ASYNC16(sb + SW_E + off, gsrc + off);
        }
        CP_COMMIT();
    }
    const float gl0 = __ldg(lnw + 2 * lane), gl1 = __ldg(lnw + 2 * lane + 1);
    const float gl2 = __ldg(lnw + 64 + 2 * lane), gl3 = __ldg(lnw + 65 + 2 * lane);
    CP_WAIT0();
    __syncthreads();

    // GEMM-warp constants (wid < 8): wq = M quad, nq = N half
    const int wq = wid & 3;
    const int nq = wid >> 2;                     // 0 or 1 for GEMM warps
    const int mbase = wq * 32;
    const uint32_t a_lane = (uint32_t)((((lane >> 3) & 1) << 11) + ((lane >> 4) << 7) + ((lane & 7) << 4));
    const uint32_t b_lane = (uint32_t)(((lane >> 4) << 11) + (((lane >> 3) & 1) << 7) + ((lane & 7) << 4));
    const int r0  = mbase + (lane >> 2);
    const int cbx = (lane & 3) * 2;
    // LN-warp constants (wid >= 8)
    const int pw = wid - 8;
    const int ptid = tid - 256;

    const int nloc = (blockIdx.x < NT_TOTAL) ? ((NT_TOTAL - 1 - (int)blockIdx.x) / (int)gridDim.x + 1) : 0;

    float q3[6], q5[10];

    for (int i = 0; i <= nloc; ++i) {
        if (wid >= 8) {
            // ================= LN / gather warps: produce W[i&1] for tile(i)
            if (i < nloc) {
                const int tile = blockIdx.x + i * (int)gridDim.x;
                const int batch = tile >> 10;          // node = tile*4; batch = node/4096
                const uint32_t wb = sb + ((i & 1) ? SW_W1 : SW_W0);
                if (ptid < 128) s_ix[ptid] = __ldg(nidx + tile * 128 + ptid);
                NB_LN();
                // prologue: chunk 0
                #pragma unroll
                for (int it = 0; it < 4; ++it) {
                    int s = it * 256 + ptid;
                    int jj = s >> 7, part = s & 127;
                    const char* src = (const char*)g_k
                        + ((size_t)(batch * 4096 + s_ix[jj]) * 2048 + (size_t)part * 16);
                    CP_ASYNC16(sb + SW_KB0 + (uint32_t)(jj * 2064 + part * 16), src);
                }
                CP_COMMIT();
                #pragma unroll 1
                for (int ch = 0; ch < 16; ++ch) {
                    if (ch < 15) {
                        const uint32_t kb = ((ch + 1) & 1) ? SW_KB1 : SW_KB0;
                        const int ib = (ch + 1) * 8;
                        #pragma unroll
                        for (int it = 0; it < 4; ++it) {
                            int s = it * 256 + ptid;
                            int jj = s >> 7, part = s & 127;
                            const char* src = (const char*)g_k
                                + ((size_t)(batch * 4096 + s_ix[ib + jj]) * 2048 + (size_t)part * 16);
                            CP_ASYNC16(sb + kb + (uint32_t)(jj * 2064 + part * 16), src);
                        }
                        CP_COMMIT();
                        CP_WAIT1();
                    } else {
                        CP_WAIT0();
                    }
                    NB_LN();
                    if ((ch & 3) == 0) {
                        const float* qp = g_q + (size_t)(tile * 4 + (ch >> 2)) * 512;
                        const float2* qa = (const float2*)(qp + 6 * lane);
                        float2 t0 = __ldg(qa), t1 = __ldg(qa + 1), t2 = __ldg(qa + 2);
                        q3[0] = t0.x; q3[1] = t0.y; q3[2] = t1.x; q3[3] = t1.y; q3[4] = t2.x; q3[5] = t2.y;
                        const float2* qb = (const float2*)(qp + 192 + 10 * lane);
                        float2 u0 = __ldg(qb), u1 = __ldg(qb + 1), u2 = __ldg(qb + 2), u3 = __ldg(qb + 3), u4 = __ldg(qb + 4);
                        q5[0] = u0.x; q5[1] = u0.y; q5[2] = u1.x; q5[3] = u1.y; q5[4] = u2.x;
                        q5[5] = u2.y; q5[6] = u3.x; q5[7] = u3.y; q5[8] = u4.x; q5[9] = u4.y;
                    }
                    const float* kr = (const float*)(smem + ((ch & 1) ? SW_KB1 : SW_KB0)) + pw * 516;
                    const int b = 6 * lane;
                    float v0 = q3[0]*kr[b] + q3[1]*kr[b+1] + q3[2]*kr[b+2];
                    float v1 = q3[3]*kr[b+3] + q3[4]*kr[b+4] + q3[5]*kr[b+5];
                    const int b2 = 192 + 10 * lane;
                    float v2 = 0.f, v3 = 0.f;
                    #pragma unroll
                    for (int m5 = 0; m5 < 5; ++m5) {
                        v2 += q5[m5] * kr[b2 + m5];
                        v3 += q5[5 + m5] * kr[b2 + 5 + m5];
                    }
                    float s  = v0 + v1 + v2 + v3;
                    float ss = v0*v0 + v1*v1 + v2*v2 + v3*v3;
                    #pragma unroll
                    for (int o = 16; o > 0; o >>= 1) {
                        s  += __shfl_xor_sync(0xffffffffu, s,  o);
                        ss += __shfl_xor_sync(0xffffffffu, ss, o);
                    }
                    const float mu = s * (1.f / 128.f);
                    const float var = ss * (1.f / 128.f) - mu * mu;
                    const float sc = rsqrtf(fmaxf(var, 0.f) + 1e-5f);
                    v0 = (v0 - mu) * sc * gl0; v1 = (v1 - mu) * sc * gl1;
                    v2 = (v2 - mu) * sc * gl2; v3 = (v3 - mu) * sc * gl3;
                    const int m = ch * 8 + pw;
                    const uint32_t off1 = (uint32_t)(((m >> 3) << 11) + ((m & 7) << 4)
                                                     + ((lane >> 2) << 7) + ((lane & 3) << 2));
                    *(uint32_t*)(smem + (wb - sb) + off1)         = pack_f16x2(v0, v1);
                    *(uint32_t*)(smem + (wb - sb) + off1 + 1024u) = pack_f16x2(v2, v3);
                    NB_LN();
                }
            }
        } else if (i >= 1) {
            // ================= GEMM warps: consume W[(i-1)&1] for tile(i-1)
            const int tile = blockIdx.x + (i - 1) * (int)gridDim.x;
            const uint32_t wb = sb + (((i - 1) & 1) ? SW_W1 : SW_W0);
            const float* tb = t_ij + (size_t)tile * 16384;
            float* ob = out + (size_t)tile * 16384;
            #pragma unroll 1
            for (int nh = 0; nh < 2; ++nh) {
                float accE[32];
                #pragma unroll
                for (int z = 0; z < 32; ++z) accE[z] = 0.f;
                // ---- edge GEMM: fp16 single pass
                #pragma unroll
                for (int ks = 0; ks < 8; ++ks) {
                    uint32_t ah[8];
                    const uint32_t aoff = a_lane + (uint32_t)(ks * 256);
                    LDSM_X4(ah[0], ah[1], ah[2], ah[3], wb + (uint32_t)((4 * wq) * 2048) + aoff);
                    LDSM_X4(ah[4], ah[5], ah[6], ah[7], wb + (uint32_t)((4 * wq + 2) * 2048) + aoff);
                    #pragma unroll
                    for (int ntp = 0; ntp < 2; ++ntp) {
                        const uint32_t boff = (uint32_t)((nq * 8 + nh * 4 + ntp * 2) << 11) + b_lane + (uint32_t)(ks << 8);
                        uint32_t e0, e1, e2, e3;
                        LDSM_X4(e0, e1, e2, e3, sb + SW_E + boff);
                        MMA_F16(&accE[((0 * 2 + ntp) * 2 + 0) * 4], ah[0], ah[1], ah[2], ah[3], e0, e1);
                        MMA_F16(&accE[((0 * 2 + ntp) * 2 + 1) * 4], ah[0], ah[1], ah[2], ah[3], e2, e3);
                        MMA_F16(&accE[((1 * 2 + ntp) * 2 + 0) * 4], ah[4], ah[5], ah[6], ah[7], e0, e1);
                        MMA_F16(&accE[((1 * 2 + ntp) * 2 + 1) * 4], ah[4], ah[5], ah[6], ah[7], e2, e3);
                    }
                }
                // ---- res GEMM: bf16 3-pass, A = T from global
                float accR[32];
                #pragma unroll
                for (int z = 0; z < 32; ++z) accR[z] = 0.f;
                #pragma unroll
                for (int ks = 0; ks < 8; ++ks) {
                    uint32_t th[8], tl[8];
                    const int col = ks * 16 + cbx;
                    #pragma unroll
                    for (int mi = 0; mi < 2; ++mi) {
                        const int rr = r0 + mi * 16;
                        float2 v0 = __ldg((const float2*)(tb + rr * 128 + col));
                        float2 v1 = __ldg((const float2*)(tb + (rr + 8) * 128 + col));
                        float2 v2 = __ldg((const float2*)(tb + rr * 128 + col + 8));
                        float2 v3 = __ldg((const float2*)(tb + (rr + 8) * 128 + col + 8));
                        uint32_t p0 = pack_bf16x2(v0.x, v0.y);
                        uint32_t p1 = pack_bf16x2(v1.x, v1.y);
                        uint32_t p2 = pack_bf16x2(v2.x, v2.y);
                        uint32_t p3 = pack_bf16x2(v3.x, v3.y);
                        th[mi * 4 + 0] = p0; th[mi * 4 + 1] = p1; th[mi * 4 + 2] = p2; th[mi * 4 + 3] = p3;
                        tl[mi * 4 + 0] = pack_bf16x2(v0.x - __uint_as_float(p0 << 16), v0.y - __uint_as_float(p0 & 0xffff0000u));
                        tl[mi * 4 + 1] = pack_bf16x2(v1.x - __uint_as_float(p1 << 16), v1.y - __uint_as_float(p1 & 0xffff0000u));
                        tl[mi * 4 + 2] = pack_bf16x2(v2.x - __uint_as_float(p2 << 16), v2.y - __uint_as_float(p2 & 0xffff0000u));
                        tl[mi * 4 + 3] = pack_bf16x2(v3.x - __uint_as_float(p3 << 16), v3.y - __uint_as_float(p3 & 0xffff0000u));
                    }
                    #pragma unroll
                    for (int ntp = 0; ntp < 2; ++ntp) {
                        const uint32_t boff = (uint32_t)((nq * 8 + nh * 4 + ntp * 2) << 11) + b_lane + (uint32_t)(ks << 8);
                        uint32_t b0, b1, b2, b3, c0, c1, c2, c3;
                        LDSM_X4(b0, b1, b2, b3, sb + SW_RH + boff);
                        MMA_BF16(&accR[((0 * 2 + ntp) * 2 + 0) * 4], th[0], th[1], th[2], th[3], b0, b1);
                        MMA_BF16(&accR[((0 * 2 + ntp) * 2 + 1) * 4], th[0], th[1], th[2], th[3], b2, b3);
                        MMA_BF16(&accR[((1 * 2 + ntp) * 2 + 0) * 4], th[4], th[5], th[6], th[7], b0, b1);
                        MMA_BF16(&accR[((1 * 2 + ntp) * 2 + 1) * 4], th[4], th[5], th[6], th[7], b2, b3);
                        MMA_BF16(&accR[((0 * 2 + ntp) * 2 + 0) * 4], tl[0], tl[1], tl[2], tl[3], b0, b1);
                        MMA_BF16(&accR[((0 * 2 + ntp) * 2 + 1) * 4], tl[0], tl[1], tl[2], tl[3], b2, b3);
                        MMA_BF16(&accR[((1 * 2 + ntp) * 2 + 0) * 4], tl[4], tl[5], tl[6], tl[7], b0, b1);
                        MMA_BF16(&accR[((1 * 2 + ntp) * 2 + 1) * 4], tl[4], tl[5], tl[6], tl[7], b2, b3);
                        LDSM_X4(c0, c1, c2, c3, sb + SW_RL + boff);
                        MMA_BF16(&accR[((0 * 2 + ntp) * 2 + 0) * 4], th[0], th[1], th[2], th[3], c0, c1);
                        MMA_BF16(&accR[((0 * 2 + ntp) * 2 + 1) * 4], th[0], th[1], th[2], th[3], c2, c3);
                        MMA_BF16(&accR[((1 * 2 + ntp) * 2 + 0) * 4], th[4], th[5], th[6], th[7], c0, c1);
                        MMA_BF16(&accR[((1 * 2 + ntp) * 2 + 1) * 4], th[4], th[5], th[6], th[7], c2, c3);
                    }
                }
                // ---- epilogue
                #pragma unroll
                for (int mi = 0; mi < 2; ++mi) {
                    #pragma unroll
                    for (int ntp = 0; ntp < 2; ++ntp) {
                        #pragma unroll
                        for (int sub = 0; sub < 2; ++sub) {
                            const int g4 = ((mi * 2 + ntp) * 2 + sub) * 4;
                            const int rr = r0 + mi * 16;
                            const int col = nq * 64 + nh * 32 + ntp * 16 + sub * 8 + cbx;
                            float o0 = 1.f / (1.f + __expf(-accE[g4 + 0])) + accR[g4 + 0];
                            float o1 = 1.f / (1.f + __expf(-accE[g4 + 1])) + accR[g4 + 1];
                            float o2 = 1.f / (1.f + __expf(-accE[g4 + 2])) + accR[g4 + 2];
                            float o3 = 1.f / (1.f + __expf(-accE[g4 + 3])) + accR[g4 + 3];
                            *(float2*)(ob + rr * 128 + col)       = make_float2(o0, o1);
                            *(float2*)(ob + (rr + 8) * 128 + col) = make_float2(o2, o3);
                        }
                    }
                }
            }
        }
        __syncthreads();   // pipeline step: swap W buffers
    }
}

// ------------------------------------------------------------------ launch
extern "C" void kernel_launch(void* const* d_in, const int* in_sizes, int n_in,
                              void* d_out, int out_size)
{
    const float* t_ij = (const float*)d_in[0];
    const float* x1   = (const float*)d_in[1];
    const float* x2   = (const float*)d_in[2];
    const int*   nidx = (const int*)  d_in[3];
    const float* tq   = (const float*)d_in[4];
    const float* tk1  = (const float*)d_in[5];
    const float* tk2  = (const float*)d_in[6];
    const float* lnw  = (const float*)d_in[7];
    const float* ew   = (const float*)d_in[8];
    const float* rw   = (const float*)d_in[9];
    float* out = (float*)d_out;

    int dev = 0, nsm = 148;
    cudaGetDevice(&dev);
    cudaDeviceGetAttribute(&nsm, cudaDevAttrMultiProcessorCount, dev);

    cudaFuncSetAttribute(prep_kernel, cudaFuncAttributeMaxDynamicSharedMemorySize, PREP_SMEM);
    cudaFuncSetAttribute(main_kernel, cudaFuncAttributeMaxDynamicSharedMemorySize, SMEM_B);

    prep_kernel<<<128 + NNODES / 32, 256, PREP_SMEM>>>(ew, rw, x1, x2, tq, tk1, tk2);
    main_kernel<<<nsm, 512, SMEM_B>>>(t_ij, nidx, lnw, out);
}

// round 10
// speedup vs baseline: 4.2180x; 1.2197x over previous
#include <cuda_runtime.h>
#include <cuda_bf16.h>
#include <cstdint>

#define NNODES 8192
#define QK_STRIDE 512
#define NT_TOTAL 2048        // 4 nodes per tile (M=128)

// ------------------------------------------------------------------ scratch
// m-major layout: g_q/g_k[node*512 + m*64 + e], m in [0,8), e in [0,64)
//   m 0..2 = ml-3 block (x1/tk1), m 3..7 = ml-5 block (x2/tk2)
__device__ __align__(16) float g_q[(size_t)NNODES * QK_STRIDE];
__device__ __align__(16) float g_k[(size_t)NNODES * QK_STRIDE];
// 3 tile-blocked weight images, 32KB each: [E fp16][Rh bf16][Rl bf16]
__device__ __align__(16) unsigned char g_wtiles[3 * 32768];

// ------------------------------------------------------------------ helpers
__device__ __forceinline__ uint32_t smem_u32(const void* p) {
    uint32_t a;
    asm("{ .reg .u64 t; cvta.to.shared.u64 t, %1; cvt.u32.u64 %0, t; }" : "=r"(a) : "l"(p));
    return a;
}
__device__ __forceinline__ uint32_t pack_bf16x2(float a, float b) {  // lo=bf16(a), hi=bf16(b)
    uint32_t p;
    asm("cvt.rn.bf16x2.f32 %0, %1, %2;" : "=r"(p) : "f"(b), "f"(a));
    return p;
}
__device__ __forceinline__ uint32_t pack_f16x2(float a, float b) {   // lo=f16(a), hi=f16(b)
    uint32_t p;
    asm("cvt.rn.f16x2.f32 %0, %1, %2;" : "=r"(p) : "f"(b), "f"(a));
    return p;
}
#define LDSM_X4(r0, r1, r2, r3, addr) \
    asm volatile("ldmatrix.sync.aligned.m8n8.x4.shared.b16 {%0,%1,%2,%3}, [%4];" \
        : "=r"(r0), "=r"(r1), "=r"(r2), "=r"(r3) : "r"(addr))
#define MMA_BF16(c, a0, a1, a2, a3, b0, b1) \
    asm volatile("mma.sync.aligned.m16n8k16.row.col.f32.bf16.bf16.f32 " \
        "{%0,%1,%2,%3}, {%4,%5,%6,%7}, {%8,%9}, {%0,%1,%2,%3};" \
        : "+f"((c)[0]), "+f"((c)[1]), "+f"((c)[2]), "+f"((c)[3]) \
        : "r"(a0), "r"(a1), "r"(a2), "r"(a3), "r"(b0), "r"(b1))
#define MMA_F16(c, a0, a1, a2, a3, b0, b1) \
    asm volatile("mma.sync.aligned.m16n8k16.row.col.f32.f16.f16.f32 " \
        "{%0,%1,%2,%3}, {%4,%5,%6,%7}, {%8,%9}, {%0,%1,%2,%3};" \
        : "+f"((c)[0]), "+f"((c)[1]), "+f"((c)[2]), "+f"((c)[3]) \
        : "r"(a0), "r"(a1), "r"(a2), "r"(a3), "r"(b0), "r"(b1))
#define CP_ASYNC16(saddr, gptr) \
    asm volatile("cp.async.cg.shared.global [%0], [%1], 16;" :: "r"(saddr), "l"(gptr))
#define CP_COMMIT() asm volatile("cp.async.commit_group;")
#define CP_WAIT0()  asm volatile("cp.async.wait_group 0;" ::: "memory")

// ------------------------------------------------------------------ main smem map (bytes)
#define SW_E   0          // 32768 fp16 edge image
#define SW_RH  32768      // 32768 bf16 res hi
#define SW_RL  65536      // 32768 bf16 res lo
#define SW_W0  98304      // 32768 fp16 W buf 0 (M=128)
#define SW_W1  131072     // 32768 fp16 W buf 1
#define SMEM_B 163840

// prep smem: [0:98304) weights tq|tk1|tk2 fp32, then x slots 16 x 1040 f32
#define PREP_SMEM (98304 + 16 * 1040 * 4)

// ------------------------------------------------------------------ kernel 0: prep = wsplit + proj
__global__ void __launch_bounds__(512) prep_kernel(
    const float* __restrict__ ew,  const float* __restrict__ rw,
    const float* __restrict__ x1,  const float* __restrict__ x2,
    const float* __restrict__ tq,  const float* __restrict__ tk1,
    const float* __restrict__ tk2)
{
    extern __shared__ char smem[];
    const int tid = threadIdx.x;
    if (blockIdx.x < 64) {
        // ---- weight split (edge/res GEMM B images)
        int id = blockIdx.x * 512 + tid;              // 0..32767
        int w = id >> 14, k = (id >> 7) & 127, n = id & 127;
        float v = (w ? rw : ew)[k * 128 + n];         // B[n][k] = W[k][n]
        uint32_t off = (uint32_t)(((n >> 3) * 8 + (k >> 4)) * 256 + (((k >> 3) & 1) << 7)
                                  + ((n & 7) << 4) + ((k & 7) << 1));
        if (w == 0) {
            uint32_t p = pack_f16x2(v, 0.f);
            *(uint16_t*)(g_wtiles + off) = (uint16_t)(p & 0xffffu);
        } else {
            uint32_t ph = pack_bf16x2(v, 0.f);
            float hf = __uint_as_float(ph << 16);
            uint32_t pl = pack_bf16x2(v - hf, 0.f);
            *(uint16_t*)(g_wtiles + 32768u + off) = (uint16_t)(ph & 0xffffu);
            *(uint16_t*)(g_wtiles + 65536u + off) = (uint16_t)(pl & 0xffffu);
        }
        return;
    }
    // ---- projections: 32 nodes per block, 16 warps, 2 nodes per warp
    float* psm = (float*)smem;
    const uint32_t sb = smem_u32(smem);
    {
        #pragma unroll
        for (int i = 0; i < 4; ++i) {
            uint32_t off = (uint32_t)(i * 8192 + tid * 16);
            CP_ASYNC16(sb + off,           (const char*)tq  + off);
            CP_ASYNC16(sb + 32768u + off,  (const char*)tk1 + off);
            CP_ASYNC16(sb + 65536u + off,  (const char*)tk2 + off);
        }
        CP_COMMIT();
    }
    const int wid = tid >> 5, lane = tid & 31;
    float* sx = psm + 24576 + wid * 1040;
    const int nbase = (blockIdx.x - 64) * 32;
    CP_WAIT0();
    __syncthreads();

    const float2* wqp  = (const float2*)psm + lane;
    const float2* wk1p = (const float2*)(psm + 8192) + lane;
    const float2* wk2p = (const float2*)(psm + 16384) + lane;

    for (int it = 0; it < 2; ++it) {
        const int node = nbase + it * 16 + wid;
        const float* px1 = x1 + (size_t)node * 384;
        const float* px2 = x2 + (size_t)node * 640;
        for (int j = lane; j < 384; j += 32) { int d = j / 3; sx[d * 8 + (j - d * 3)] = __ldg(px1 + j); }
        for (int j = lane; j < 640; j += 32) { int d = j / 5; sx[d * 8 + 3 + (j - d * 5)] = __ldg(px2 + j); }
        __syncwarp();

        float aq[16], ak[16];   // [m][e0/e1], e0=2*lane, e1=2*lane+1
        #pragma unroll
        for (int i = 0; i < 16; ++i) { aq[i] = 0.f; ak[i] = 0.f; }
        #pragma unroll 4
        for (int d = 0; d < 128; ++d) {
            const float2 w_q = wqp[d * 32];
            const float2 w_1 = wk1p[d * 32];
            const float2 w_2 = wk2p[d * 32];
            const float2* xr = (const float2*)(sx + d * 8);
            float2 x01 = xr[0], x23 = xr[1], x45 = xr[2], x67 = xr[3];
            const float xs[8] = {x01.x, x01.y, x23.x, x23.y, x45.x, x45.y, x67.x, x67.y};
            #pragma unroll
            for (int m = 0; m < 8; ++m) {
                aq[m * 2]     += w_q.x * xs[m];
                aq[m * 2 + 1] += w_q.y * xs[m];
                const float wk0  = (m < 3) ? w_1.x : w_2.x;
                const float wk1v = (m < 3) ? w_1.y : w_2.y;
                ak[m * 2]     += wk0  * xs[m];
                ak[m * 2 + 1] += wk1v * xs[m];
            }
        }
        // m-major coalesced stores
        float* oq = g_q + (size_t)node * QK_STRIDE + 2 * lane;
        float* ok = g_k + (size_t)node * QK_STRIDE + 2 * lane;
        #pragma unroll
        for (int m = 0; m < 8; ++m) {
            *(float2*)(oq + m * 64) = make_float2(aq[m * 2], aq[m * 2 + 1]);
            *(float2*)(ok + m * 64) = make_float2(ak[m * 2], ak[m * 2 + 1]);
        }
        __syncwarp();
    }
}

// ------------------------------------------------------------------ kernel 1: warp-specialized persistent main
__global__ void __launch_bounds__(512, 1) main_kernel(
    const float* __restrict__ t_ij, const int* __restrict__ nidx,
    const float* __restrict__ lnw, float* __restrict__ out)
{
    extern __shared__ char smem[];
    const uint32_t sb = smem_u32(smem);
    const int tid = threadIdx.x, lane = tid & 31, wid = tid >> 5;

    // ---- stage weight images ONCE (96 KB)
    {
        const char* gsrc = (const char*)g_wtiles;
        #pragma unroll
        for (int i = 0; i < 12; ++i) {
            uint32_t off = (uint32_t)(i * 8192 + tid * 16);
            CP_ASYNC16(sb + SW_E + off, gsrc + off);
        }
        CP_COMMIT();
    }
    const float gl0 = __ldg(lnw + 2 * lane), gl1 = __ldg(lnw + 2 * lane + 1);
    const float gl2 = __ldg(lnw + 64 + 2 * lane), gl3 = __ldg(lnw + 65 + 2 * lane);
    CP_WAIT0();
    __syncthreads();

    // GEMM-warp constants (wid < 8): wq = M quad, nq = N half
    const int wq = wid & 3;
    const int nq = wid >> 2;
    const int mbase = wq * 32;
    const uint32_t a_lane = (uint32_t)((((lane >> 3) & 1) << 11) + ((lane >> 4) << 7) + ((lane & 7) << 4));
    const uint32_t b_lane = (uint32_t)(((lane >> 4) << 11) + (((lane >> 3) & 1) << 7) + ((lane & 7) << 4));
    const int r0  = mbase + (lane >> 2);
    const int cbx = (lane & 3) * 2;
    // LN-warp constants (wid >= 8)
    const int pw = wid - 8;

    const int nloc = (blockIdx.x < NT_TOTAL) ? ((NT_TOTAL - 1 - (int)blockIdx.x) / (int)gridDim.x + 1) : 0;

    for (int i = 0; i <= nloc; ++i) {
        if (wid >= 8) {
            // ================= LN warps: produce W[i&1] for tile(i), rows pw*16..pw*16+15
            if (i < nloc) {
                const int tile = blockIdx.x + i * (int)gridDim.x;
                const int batch = tile >> 10;
                char* wbp = smem + ((i & 1) ? SW_W1 : SW_W0);
                const int m0 = pw * 16;
                const int node = tile * 4 + (m0 >> 5);

                // q for this warp's node (all 16 rows share it)
                const float* qp = g_q + (size_t)node * 512 + 2 * lane;
                float2 q[8];
                #pragma unroll
                for (int m = 0; m < 8; ++m) q[m] = __ldg((const float2*)(qp + m * 64));

                // neighbor indices (uniform loads, 2 sectors)
                const int* ixp = nidx + tile * 128 + m0;
                int idxv[16];
                #pragma unroll
                for (int rr = 0; rr < 16; ++rr) idxv[rr] = __ldg(ixp + rr);

                const float* kbase = g_k + (size_t)batch * 4096 * 512 + 2 * lane;
                float2 kn[8];
                {
                    const float* kp = kbase + (size_t)idxv[0] * 512;
                    #pragma unroll
                    for (int m = 0; m < 8; ++m) kn[m] = __ldg((const float2*)(kp + m * 64));
                }
                #pragma unroll
                for (int rr = 0; rr < 16; ++rr) {
                    float2 kc[8];
                    #pragma unroll
                    for (int m = 0; m < 8; ++m) kc[m] = kn[m];
                    if (rr < 15) {
                        const float* kp = kbase + (size_t)idxv[rr + 1] * 512;
                        #pragma unroll
                        for (int m = 0; m < 8; ++m) kn[m] = __ldg((const float2*)(kp + m * 64));
                    }
                    float v0 = q[0].x*kc[0].x + q[1].x*kc[1].x + q[2].x*kc[2].x;
                    float v1 = q[0].y*kc[0].y + q[1].y*kc[1].y + q[2].y*kc[2].y;
                    float v2 = q[3].x*kc[3].x + q[4].x*kc[4].x + q[5].x*kc[5].x + q[6].x*kc[6].x + q[7].x*kc[7].x;
                    float v3 = q[3].y*kc[3].y + q[4].y*kc[4].y + q[5].y*kc[5].y + q[6].y*kc[6].y + q[7].y*kc[7].y;
                    float s  = v0 + v1 + v2 + v3;
                    float ss = v0*v0 + v1*v1 + v2*v2 + v3*v3;
                    #pragma unroll
                    for (int o = 16; o > 0; o >>= 1) {
                        s  += __shfl_xor_sync(0xffffffffu, s,  o);
                        ss += __shfl_xor_sync(0xffffffffu, ss, o);
                    }
                    const float mu = s * (1.f / 128.f);
                    const float var = ss * (1.f / 128.f) - mu * mu;
                    const float sc = rsqrtf(fmaxf(var, 0.f) + 1e-5f);
                    v0 = (v0 - mu) * sc * gl0; v1 = (v1 - mu) * sc * gl1;
                    v2 = (v2 - mu) * sc * gl2; v3 = (v3 - mu) * sc * gl3;
                    const int m = m0 + rr;
                    const uint32_t off1 = (uint32_t)(((m >> 3) << 11) + ((m & 7) << 4)
                                                     + ((lane >> 2) << 7) + ((lane & 3) << 2));
                    *(uint32_t*)(wbp + off1)         = pack_f16x2(v0, v1);
                    *(uint32_t*)(wbp + off1 + 1024u) = pack_f16x2(v2, v3);
                }
            }
        } else if (i >= 1) {
            // ================= GEMM warps: consume W[(i-1)&1] for tile(i-1)
            const int tile = blockIdx.x + (i - 1) * (int)gridDim.x;
            const uint32_t wb = sb + (((i - 1) & 1) ? SW_W1 : SW_W0);
            const float* tb = t_ij + (size_t)tile * 16384;
            float* ob = out + (size_t)tile * 16384;
            #pragma unroll 1
            for (int nh = 0; nh < 2; ++nh) {
                float accE[32];
                #pragma unroll
                for (int z = 0; z < 32; ++z) accE[z] = 0.f;
                // ---- edge GEMM: fp16 single pass
                #pragma unroll
                for (int ks = 0; ks < 8; ++ks) {
                    uint32_t ah[8];
                    const uint32_t aoff = a_lane + (uint32_t)(ks * 256);
                    LDSM_X4(ah[0], ah[1], ah[2], ah[3], wb + (uint32_t)((4 * wq) * 2048) + aoff);
                    LDSM_X4(ah[4], ah[5], ah[6], ah[7], wb + (uint32_t)((4 * wq + 2) * 2048) + aoff);
                    #pragma unroll
                    for (int ntp = 0; ntp < 2; ++ntp) {
                        const uint32_t boff = (uint32_t)((nq * 8 + nh * 4 + ntp * 2) << 11) + b_lane + (uint32_t)(ks << 8);
                        uint32_t e0, e1, e2, e3;
                        LDSM_X4(e0, e1, e2, e3, sb + SW_E + boff);
                        MMA_F16(&accE[((0 * 2 + ntp) * 2 + 0) * 4], ah[0], ah[1], ah[2], ah[3], e0, e1);
                        MMA_F16(&accE[((0 * 2 + ntp) * 2 + 1) * 4], ah[0], ah[1], ah[2], ah[3], e2, e3);
                        MMA_F16(&accE[((1 * 2 + ntp) * 2 + 0) * 4], ah[4], ah[5], ah[6], ah[7], e0, e1);
                        MMA_F16(&accE[((1 * 2 + ntp) * 2 + 1) * 4], ah[4], ah[5], ah[6], ah[7], e2, e3);
                    }
                }
                // ---- res GEMM: bf16 3-pass, A = T from global
                float accR[32];
                #pragma unroll
                for (int z = 0; z < 32; ++z) accR[z] = 0.f;
                #pragma unroll
                for (int ks = 0; ks < 8; ++ks) {
                    uint32_t th[8], tl[8];
                    const int col = ks * 16 + cbx;
                    #pragma unroll
                    for (int mi = 0; mi < 2; ++mi) {
                        const int rr = r0 + mi * 16;
                        float2 v0 = __ldg((const float2*)(tb + rr * 128 + col));
                        float2 v1 = __ldg((const float2*)(tb + (rr + 8) * 128 + col));
                        float2 v2 = __ldg((const float2*)(tb + rr * 128 + col + 8));
                        float2 v3 = __ldg((const float2*)(tb + (rr + 8) * 128 + col + 8));
                        uint32_t p0 = pack_bf16x2(v0.x, v0.y);
                        uint32_t p1 = pack_bf16x2(v1.x, v1.y);
                        uint32_t p2 = pack_bf16x2(v2.x, v2.y);
                        uint32_t p3 = pack_bf16x2(v3.x, v3.y);
                        th[mi * 4 + 0] = p0; th[mi * 4 + 1] = p1; th[mi * 4 + 2] = p2; th[mi * 4 + 3] = p3;
                        tl[mi * 4 + 0] = pack_bf16x2(v0.x - __uint_as_float(p0 << 16), v0.y - __uint_as_float(p0 & 0xffff0000u));
                        tl[mi * 4 + 1] = pack_bf16x2(v1.x - __uint_as_float(p1 << 16), v1.y - __uint_as_float(p1 & 0xffff0000u));
                        tl[mi * 4 + 2] = pack_bf16x2(v2.x - __uint_as_float(p2 << 16), v2.y - __uint_as_float(p2 & 0xffff0000u));
                        tl[mi * 4 + 3] = pack_bf16x2(v3.x - __uint_as_float(p3 << 16), v3.y - __uint_as_float(p3 & 0xffff0000u));
                    }
                    #pragma unroll
                    for (int ntp = 0; ntp < 2; ++ntp) {
                        const uint32_t boff = (uint32_t)((nq * 8 + nh * 4 + ntp * 2) << 11) + b_lane + (uint32_t)(ks << 8);
                        uint32_t b0, b1, b2, b3, c0, c1, c2, c3;
                        LDSM_X4(b0, b1, b2, b3, sb + SW_RH + boff);
                        MMA_BF16(&accR[((0 * 2 + ntp) * 2 + 0) * 4], th[0], th[1], th[2], th[3], b0, b1);
                        MMA_BF16(&accR[((0 * 2 + ntp) * 2 + 1) * 4], th[0], th[1], th[2], th[3], b2, b3);
                        MMA_BF16(&accR[((1 * 2 + ntp) * 2 + 0) * 4], th[4], th[5], th[6], th[7], b0, b1);
                        MMA_BF16(&accR[((1 * 2 + ntp) * 2 + 1) * 4], th[4], th[5], th[6], th[7], b2, b3);
                        MMA_BF16(&accR[((0 * 2 + ntp) * 2 + 0) * 4], tl[0], tl[1], tl[2], tl[3], b0, b1);
                        MMA_BF16(&accR[((0 * 2 + ntp) * 2 + 1) * 4], tl[0], tl[1], tl[2], tl[3], b2, b3);
                        MMA_BF16(&accR[((1 * 2 + ntp) * 2 + 0) * 4], tl[4], tl[5], tl[6], tl[7], b0, b1);
                        MMA_BF16(&accR[((1 * 2 + ntp) * 2 + 1) * 4], tl[4], tl[5], tl[6], tl[7], b2, b3);
                        LDSM_X4(c0, c1, c2, c3, sb + SW_RL + boff);
                        MMA_BF16(&accR[((0 * 2 + ntp) * 2 + 0) * 4], th[0], th[1], th[2], th[3], c0, c1);
                        MMA_BF16(&accR[((0 * 2 + ntp) * 2 + 1) * 4], th[0], th[1], th[2], th[3], c2, c3);
                        MMA_BF16(&accR[((1 * 2 + ntp) * 2 + 0) * 4], th[4], th[5], th[6], th[7], c0, c1);
                        MMA_BF16(&accR[((1 * 2 + ntp) * 2 + 1) * 4], th[4], th[5], th[6], th[7], c2, c3);
                    }
                }
                // ---- epilogue
                #pragma unroll
                for (int mi = 0; mi < 2; ++mi) {
                    #pragma unroll
                    for (int ntp = 0; ntp < 2; ++ntp) {
                        #pragma unroll
                        for (int sub = 0; sub < 2; ++sub) {
                            const int g4 = ((mi * 2 + ntp) * 2 + sub) * 4;
                            const int rr = r0 + mi * 16;
                            const int col = nq * 64 + nh * 32 + ntp * 16 + sub * 8 + cbx;
                            float o0 = 1.f / (1.f + __expf(-accE[g4 + 0])) + accR[g4 + 0];
                            float o1 = 1.f / (1.f + __expf(-accE[g4 + 1])) + accR[g4 + 1];
                            float o2 = 1.f / (1.f + __expf(-accE[g4 + 2])) + accR[g4 + 2];
                            float o3 = 1.f / (1.f + __expf(-accE[g4 + 3])) + accR[g4 + 3];
                            *(float2*)(ob + rr * 128 + col)       = make_float2(o0, o1);
                            *(float2*)(ob + (rr + 8) * 128 + col) = make_float2(o2, o3);
                        }
                    }
                }
            }
        }
        __syncthreads();   // pipeline step: swap W buffers
    }
}

// ------------------------------------------------------------------ launch
extern "C" void kernel_launch(void* const* d_in, const int* in_sizes, int n_in,
                              void* d_out, int out_size)
{
    const float* t_ij = (const float*)d_in[0];
    const float* x1   = (const float*)d_in[1];
    const float* x2   = (const float*)d_in[2];
    const int*   nidx = (const int*)  d_in[3];
    const float* tq   = (const float*)d_in[4];
    const float* tk1  = (const float*)d_in[5];
    const float* tk2  = (const float*)d_in[6];
    const float* lnw  = (const float*)d_in[7];
    const float* ew   = (const float*)d_in[8];
    const float* rw   = (const float*)d_in[9];
    float* out = (float*)d_out;

    int dev = 0, nsm = 148;
    cudaGetDevice(&dev);
    cudaDeviceGetAttribute(&nsm, cudaDevAttrMultiProcessorCount, dev);

    cudaFuncSetAttribute(prep_kernel, cudaFuncAttributeMaxDynamicSharedMemorySize, PREP_SMEM);
    cudaFuncSetAttribute(main_kernel, cudaFuncAttributeMaxDynamicSharedMemorySize, SMEM_B);

    prep_kernel<<<64 + NNODES / 32, 512, PREP_SMEM>>>(ew, rw, x1, x2, tq, tk1, tk2);
    main_kernel<<<nsm, 512, SMEM_B>>>(t_ij, nidx, lnw, out);
}

// round 11
// speedup vs baseline: 4.6582x; 1.1044x over previous
#include <cuda_runtime.h>
#include <cuda_bf16.h>
#include <cstdint>

#define NNODES 8192
#define QK_STRIDE 512
#define NT_TOTAL 2048        // 4 nodes per tile (M=128)

// ------------------------------------------------------------------ scratch
// m-major layout: g_q/g_k[node*512 + m*64 + e], m in [0,8), e in [0,64)
__device__ __align__(16) float g_q[(size_t)NNODES * QK_STRIDE];
__device__ __align__(16) float g_k[(size_t)NNODES * QK_STRIDE];
// 2 tile-blocked fp16 weight images, 32KB each: [E][R]
__device__ __align__(16) unsigned char g_wtiles[2 * 32768];

// ------------------------------------------------------------------ helpers
__device__ __forceinline__ uint32_t smem_u32(const void* p) {
    uint32_t a;
    asm("{ .reg .u64 t; cvta.to.shared.u64 t, %1; cvt.u32.u64 %0, t; }" : "=r"(a) : "l"(p));
    return a;
}
__device__ __forceinline__ uint32_t pack_f16x2(float a, float b) {   // lo=f16(a), hi=f16(b)
    uint32_t p;
    asm("cvt.rn.f16x2.f32 %0, %1, %2;" : "=r"(p) : "f"(b), "f"(a));
    return p;
}
#define LDSM_X4(r0, r1, r2, r3, addr) \
    asm volatile("ldmatrix.sync.aligned.m8n8.x4.shared.b16 {%0,%1,%2,%3}, [%4];" \
        : "=r"(r0), "=r"(r1), "=r"(r2), "=r"(r3) : "r"(addr))
#define MMA_F16(c, a0, a1, a2, a3, b0, b1) \
    asm volatile("mma.sync.aligned.m16n8k16.row.col.f32.f16.f16.f32 " \
        "{%0,%1,%2,%3}, {%4,%5,%6,%7}, {%8,%9}, {%0,%1,%2,%3};" \
        : "+f"((c)[0]), "+f"((c)[1]), "+f"((c)[2]), "+f"((c)[3]) \
        : "r"(a0), "r"(a1), "r"(a2), "r"(a3), "r"(b0), "r"(b1))
#define CP_ASYNC16(saddr, gptr) \
    asm volatile("cp.async.cg.shared.global [%0], [%1], 16;" :: "r"(saddr), "l"(gptr))
#define CP_COMMIT() asm volatile("cp.async.commit_group;")
#define CP_WAIT0()  asm volatile("cp.async.wait_group 0;" ::: "memory")

// ------------------------------------------------------------------ main smem map (bytes)
#define SW_E   0          // 32768 fp16 edge image
#define SW_R   32768      // 32768 fp16 res image
#define SW_W0  65536      // 32768 fp16 W buf 0 (M=128)
#define SW_W1  98304      // 32768 fp16 W buf 1
#define SMEM_B 131072

// prep smem: [0:98304) weights tq|tk1|tk2 fp32, then x slots 16 x 1040 f32
#define PREP_SMEM (98304 + 16 * 1040 * 4)

// ------------------------------------------------------------------ kernel 0: prep = wsplit + proj
__global__ void __launch_bounds__(512) prep_kernel(
    const float* __restrict__ ew,  const float* __restrict__ rw,
    const float* __restrict__ x1,  const float* __restrict__ x2,
    const float* __restrict__ tq,  const float* __restrict__ tk1,
    const float* __restrict__ tk2)
{
    extern __shared__ char smem[];
    const int tid = threadIdx.x;
    if (blockIdx.x < 64) {
        // ---- weight conversion (edge/res GEMM B images, fp16)
        int id = blockIdx.x * 512 + tid;              // 0..32767
        int w = id >> 14, k = (id >> 7) & 127, n = id & 127;
        float v = (w ? rw : ew)[k * 128 + n];         // B[n][k] = W[k][n]
        uint32_t off = (uint32_t)(((n >> 3) * 8 + (k >> 4)) * 256 + (((k >> 3) & 1) << 7)
                                  + ((n & 7) << 4) + ((k & 7) << 1));
        uint32_t p = pack_f16x2(v, 0.f);
        *(uint16_t*)(g_wtiles + (size_t)w * 32768 + off) = (uint16_t)(p & 0xffffu);
        return;
    }
    // ---- projections: 32 nodes per block, 16 warps, 2 nodes per warp
    float* psm = (float*)smem;
    const uint32_t sb = smem_u32(smem);
    {
        #pragma unroll
        for (int i = 0; i < 4; ++i) {
            uint32_t off = (uint32_t)(i * 8192 + tid * 16);
            CP_ASYNC16(sb + off,           (const char*)tq  + off);
            CP_ASYNC16(sb + 32768u + off,  (const char*)tk1 + off);
            CP_ASYNC16(sb + 65536u + off,  (const char*)tk2 + off);
        }
        CP_COMMIT();
    }
    const int wid = tid >> 5, lane = tid & 31;
    float* sx = psm + 24576 + wid * 1040;
    const int nbase = (blockIdx.x - 64) * 32;
    CP_WAIT0();
    __syncthreads();

    const float2* wqp  = (const float2*)psm + lane;
    const float2* wk1p = (const float2*)(psm + 8192) + lane;
    const float2* wk2p = (const float2*)(psm + 16384) + lane;

    for (int it = 0; it < 2; ++it) {
        const int node = nbase + it * 16 + wid;
        const float* px1 = x1 + (size_t)node * 384;
        const float* px2 = x2 + (size_t)node * 640;
        for (int j = lane; j < 384; j += 32) { int d = j / 3; sx[d * 8 + (j - d * 3)] = __ldg(px1 + j); }
        for (int j = lane; j < 640; j += 32) { int d = j / 5; sx[d * 8 + 3 + (j - d * 5)] = __ldg(px2 + j); }
        __syncwarp();

        float aq[16], ak[16];   // [m][e0/e1], e0=2*lane, e1=2*lane+1
        #pragma unroll
        for (int i = 0; i < 16; ++i) { aq[i] = 0.f; ak[i] = 0.f; }
        #pragma unroll 4
        for (int d = 0; d < 128; ++d) {
            const float2 w_q = wqp[d * 32];
            const float2 w_1 = wk1p[d * 32];
            const float2 w_2 = wk2p[d * 32];
            const float2* xr = (const float2*)(sx + d * 8);
            float2 x01 = xr[0], x23 = xr[1], x45 = xr[2], x67 = xr[3];
            const float xs[8] = {x01.x, x01.y, x23.x, x23.y, x45.x, x45.y, x67.x, x67.y};
            #pragma unroll
            for (int m = 0; m < 8; ++m) {
                aq[m * 2]     += w_q.x * xs[m];
                aq[m * 2 + 1] += w_q.y * xs[m];
                const float wk0  = (m < 3) ? w_1.x : w_2.x;
                const float wk1v = (m < 3) ? w_1.y : w_2.y;
                ak[m * 2]     += wk0  * xs[m];
                ak[m * 2 + 1] += wk1v * xs[m];
            }
        }
        // m-major coalesced stores
        float* oq = g_q + (size_t)node * QK_STRIDE + 2 * lane;
        float* ok = g_k + (size_t)node * QK_STRIDE + 2 * lane;
        #pragma unroll
        for (int m = 0; m < 8; ++m) {
            *(float2*)(oq + m * 64) = make_float2(aq[m * 2], aq[m * 2 + 1]);
            *(float2*)(ok + m * 64) = make_float2(ak[m * 2], ak[m * 2 + 1]);
        }
        __syncwarp();
    }
}

// ------------------------------------------------------------------ kernel 1: warp-specialized persistent main
__global__ void __launch_bounds__(512, 1) main_kernel(
    const float* __restrict__ t_ij, const int* __restrict__ nidx,
    const float* __restrict__ lnw, float* __restrict__ out)
{
    extern __shared__ char smem[];
    const uint32_t sb = smem_u32(smem);
    const int tid = threadIdx.x, lane = tid & 31, wid = tid >> 5;

    // ---- stage weight images ONCE (64 KB)
    {
        const char* gsrc = (const char*)g_wtiles;
        #pragma unroll
        for (int i = 0; i < 8; ++i) {
            uint32_t off = (uint32_t)(i * 8192 + tid * 16);
            CP_ASYNC16(sb + SW_E + off, gsrc + off);
        }
        CP_COMMIT();
    }
    const float gl0 = __ldg(lnw + 2 * lane), gl1 = __ldg(lnw + 2 * lane + 1);
    const float gl2 = __ldg(lnw + 64 + 2 * lane), gl3 = __ldg(lnw + 65 + 2 * lane);
    CP_WAIT0();
    __syncthreads();

    // GEMM-warp constants (wid < 8): wq = M quad, nq = N half
    const int wq = wid & 3;
    const int nq = wid >> 2;
    const int mbase = wq * 32;
    const uint32_t a_lane = (uint32_t)((((lane >> 3) & 1) << 11) + ((lane >> 4) << 7) + ((lane & 7) << 4));
    const uint32_t b_lane = (uint32_t)(((lane >> 4) << 11) + (((lane >> 3) & 1) << 7) + ((lane & 7) << 4));
    const int r0  = mbase + (lane >> 2);
    const int cbx = (lane & 3) * 2;
    // LN-warp constants (wid >= 8)
    const int pw = wid - 8;

    const int nloc = (blockIdx.x < NT_TOTAL) ? ((NT_TOTAL - 1 - (int)blockIdx.x) / (int)gridDim.x + 1) : 0;

    for (int i = 0; i <= nloc; ++i) {
        if (wid >= 8) {
            // ================= LN warps: produce W[i&1] for tile(i), rows pw*16..pw*16+15
            if (i < nloc) {
                const int tile = blockIdx.x + i * (int)gridDim.x;
                const int batch = tile >> 10;
                char* wbp = smem + ((i & 1) ? SW_W1 : SW_W0);
                const int m0 = pw * 16;
                const int node = tile * 4 + (m0 >> 5);

                // q for this warp's node (all 16 rows share it)
                const float* qp = g_q + (size_t)node * 512 + 2 * lane;
                float2 q[8];
                #pragma unroll
                for (int m = 0; m < 8; ++m) q[m] = __ldg((const float2*)(qp + m * 64));

                // neighbor indices (uniform loads)
                const int* ixp = nidx + tile * 128 + m0;
                int idxv[16];
                #pragma unroll
                for (int rr = 0; rr < 16; ++rr) idxv[rr] = __ldg(ixp + rr);

                const float* kbase = g_k + (size_t)batch * 4096 * 512 + 2 * lane;
                float2 kn[8];
                {
                    const float* kp = kbase + (size_t)idxv[0] * 512;
                    #pragma unroll
                    for (int m = 0; m < 8; ++m) kn[m] = __ldg((const float2*)(kp + m * 64));
                }
                #pragma unroll
                for (int rr = 0; rr < 16; ++rr) {
                    float2 kc[8];
                    #pragma unroll
                    for (int m = 0; m < 8; ++m) kc[m] = kn[m];
                    if (rr < 15) {
                        const float* kp = kbase + (size_t)idxv[rr + 1] * 512;
                        #pragma unroll
                        for (int m = 0; m < 8; ++m) kn[m] = __ldg((const float2*)(kp + m * 64));
                    }
                    float v0 = q[0].x*kc[0].x + q[1].x*kc[1].x + q[2].x*kc[2].x;
                    float v1 = q[0].y*kc[0].y + q[1].y*kc[1].y + q[2].y*kc[2].y;
                    float v2 = q[3].x*kc[3].x + q[4].x*kc[4].x + q[5].x*kc[5].x + q[6].x*kc[6].x + q[7].x*kc[7].x;
                    float v3 = q[3].y*kc[3].y + q[4].y*kc[4].y + q[5].y*kc[5].y + q[6].y*kc[6].y + q[7].y*kc[7].y;
                    float s  = v0 + v1 + v2 + v3;
                    float ss = v0*v0 + v1*v1 + v2*v2 + v3*v3;
                    #pragma unroll
                    for (int o = 16; o > 0; o >>= 1) {
                        s  += __shfl_xor_sync(0xffffffffu, s,  o);
                        ss += __shfl_xor_sync(0xffffffffu, ss, o);
                    }
                    const float mu = s * (1.f / 128.f);
                    const float var = ss * (1.f / 128.f) - mu * mu;
                    const float sc = rsqrtf(fmaxf(var, 0.f) + 1e-5f);
                    v0 = (v0 - mu) * sc * gl0; v1 = (v1 - mu) * sc * gl1;
                    v2 = (v2 - mu) * sc * gl2; v3 = (v3 - mu) * sc * gl3;
                    const int m = m0 + rr;
                    const uint32_t off1 = (uint32_t)(((m >> 3) << 11) + ((m & 7) << 4)
                                                     + ((lane >> 2) << 7) + ((lane & 3) << 2));
                    *(uint32_t*)(wbp + off1)         = pack_f16x2(v0, v1);
                    *(uint32_t*)(wbp + off1 + 1024u) = pack_f16x2(v2, v3);
                }
            }
        } else if (i >= 1) {
            // ================= GEMM warps: consume W[(i-1)&1] for tile(i-1)
            const int tile = blockIdx.x + (i - 1) * (int)gridDim.x;
            const uint32_t wb = sb + (((i - 1) & 1) ? SW_W1 : SW_W0);
            const float* tb = t_ij + (size_t)tile * 16384;
            float* ob = out + (size_t)tile * 16384;
            #pragma unroll 1
            for (int nh = 0; nh < 2; ++nh) {
                float accE[32], accR[32];
                #pragma unroll
                for (int z = 0; z < 32; ++z) { accE[z] = 0.f; accR[z] = 0.f; }
                // ---- edge GEMM: fp16 single pass (A = normalized W from smem)
                #pragma unroll
                for (int ks = 0; ks < 8; ++ks) {
                    uint32_t ah[8];
                    const uint32_t aoff = a_lane + (uint32_t)(ks * 256);
                    LDSM_X4(ah[0], ah[1], ah[2], ah[3], wb + (uint32_t)((4 * wq) * 2048) + aoff);
                    LDSM_X4(ah[4], ah[5], ah[6], ah[7], wb + (uint32_t)((4 * wq + 2) * 2048) + aoff);
                    #pragma unroll
                    for (int ntp = 0; ntp < 2; ++ntp) {
                        const uint32_t boff = (uint32_t)((nq * 8 + nh * 4 + ntp * 2) << 11) + b_lane + (uint32_t)(ks << 8);
                        uint32_t e0, e1, e2, e3;
                        LDSM_X4(e0, e1, e2, e3, sb + SW_E + boff);
                        MMA_F16(&accE[((0 * 2 + ntp) * 2 + 0) * 4], ah[0], ah[1], ah[2], ah[3], e0, e1);
                        MMA_F16(&accE[((0 * 2 + ntp) * 2 + 1) * 4], ah[0], ah[1], ah[2], ah[3], e2, e3);
                        MMA_F16(&accE[((1 * 2 + ntp) * 2 + 0) * 4], ah[4], ah[5], ah[6], ah[7], e0, e1);
                        MMA_F16(&accE[((1 * 2 + ntp) * 2 + 1) * 4], ah[4], ah[5], ah[6], ah[7], e2, e3);
                    }
                }
                // ---- res GEMM: fp16 single pass (A = T from global)
                #pragma unroll
                for (int ks = 0; ks < 8; ++ks) {
                    uint32_t th[8];
                    const int col = ks * 16 + cbx;
                    #pragma unroll
                    for (int mi = 0; mi < 2; ++mi) {
                        const int rr = r0 + mi * 16;
                        float2 v0 = __ldg((const float2*)(tb + rr * 128 + col));
                        float2 v1 = __ldg((const float2*)(tb + (rr + 8) * 128 + col));
                        float2 v2 = __ldg((const float2*)(tb + rr * 128 + col + 8));
                        float2 v3 = __ldg((const float2*)(tb + (rr + 8) * 128 + col + 8));
                        th[mi * 4 + 0] = pack_f16x2(v0.x, v0.y);
                        th[mi * 4 + 1] = pack_f16x2(v1.x, v1.y);
                        th[mi * 4 + 2] = pack_f16x2(v2.x, v2.y);
                        th[mi * 4 + 3] = pack_f16x2(v3.x, v3.y);
                    }
                    #pragma unroll
                    for (int ntp = 0; ntp < 2; ++ntp) {
                        const uint32_t boff = (uint32_t)((nq * 8 + nh * 4 + ntp * 2) << 11) + b_lane + (uint32_t)(ks << 8);
                        uint32_t b0, b1, b2, b3;
                        LDSM_X4(b0, b1, b2, b3, sb + SW_R + boff);
                        MMA_F16(&accR[((0 * 2 + ntp) * 2 + 0) * 4], th[0], th[1], th[2], th[3], b0, b1);
                        MMA_F16(&accR[((0 * 2 + ntp) * 2 + 1) * 4], th[0], th[1], th[2], th[3], b2, b3);
                        MMA_F16(&accR[((1 * 2 + ntp) * 2 + 0) * 4], th[4], th[5], th[6], th[7], b0, b1);
                        MMA_F16(&accR[((1 * 2 + ntp) * 2 + 1) * 4], th[4], th[5], th[6], th[7], b2, b3);
                    }
                }
                // ---- epilogue
                #pragma unroll
                for (int mi = 0; mi < 2; ++mi) {
                    #pragma unroll
                    for (int ntp = 0; ntp < 2; ++ntp) {
                        #pragma unroll
                        for (int sub = 0; sub < 2; ++sub) {
                            const int g4 = ((mi * 2 + ntp) * 2 + sub) * 4;
                            const int rr = r0 + mi * 16;
                            const int col = nq * 64 + nh * 32 + ntp * 16 + sub * 8 + cbx;
                            float o0 = 1.f / (1.f + __expf(-accE[g4 + 0])) + accR[g4 + 0];
                            float o1 = 1.f / (1.f + __expf(-accE[g4 + 1])) + accR[g4 + 1];
                            float o2 = 1.f / (1.f + __expf(-accE[g4 + 2])) + accR[g4 + 2];
                            float o3 = 1.f / (1.f + __expf(-accE[g4 + 3])) + accR[g4 + 3];
                            *(float2*)(ob + rr * 128 + col)       = make_float2(o0, o1);
                            *(float2*)(ob + (rr + 8) * 128 + col) = make_float2(o2, o3);
                        }
                    }
                }
            }
        }
        __syncthreads();   // pipeline step: swap W buffers
    }
}

// ------------------------------------------------------------------ launch
extern "C" void kernel_launch(void* const* d_in, const int* in_sizes, int n_in,
                              void* d_out, int out_size)
{
    const float* t_ij = (const float*)d_in[0];
    const float* x1   = (const float*)d_in[1];
    const float* x2   = (const float*)d_in[2];
    const int*   nidx = (const int*)  d_in[3];
    const float* tq   = (const float*)d_in[4];
    const float* tk1  = (const float*)d_in[5];
    const float* tk2  = (const float*)d_in[6];
    const float* lnw  = (const float*)d_in[7];
    const float* ew   = (const float*)d_in[8];
    const float* rw   = (const float*)d_in[9];
    float* out = (float*)d_out;

    int dev = 0, nsm = 148;
    cudaGetDevice(&dev);
    cudaDeviceGetAttribute(&nsm, cudaDevAttrMultiProcessorCount, dev);

    cudaFuncSetAttribute(prep_kernel, cudaFuncAttributeMaxDynamicSharedMemorySize, PREP_SMEM);
    cudaFuncSetAttribute(main_kernel, cudaFuncAttributeMaxDynamicSharedMemorySize, SMEM_B);

    prep_kernel<<<64 + NNODES / 32, 512, PREP_SMEM>>>(ew, rw, x1, x2, tq, tk1, tk2);
    main_kernel<<<nsm, 512, SMEM_B>>>(t_ij, nidx, lnw, out);
}